// round 1
// baseline (speedup 1.0000x reference)
#include <cuda_runtime.h>

// Linear causal attention, chunked state formulation.
// O = (tril ⊙ QK^T) V  ==  per chunk c:  Q_c @ S_c  +  (tril ⊙ Q_c K_c^T) @ V_c
// where S_c = sum_{c'<c} K_{c'}^T V_{c'}   (exclusive prefix of per-chunk states)

#define B_  4
#define H_  16
#define T_  2048
#define D_  128
#define C_  128
#define NC_ (T_ / C_)        // 16 chunks per (b,h)
#define BH_ (B_ * H_)        // 64
#define NCHUNK_ (BH_ * NC_)  // 1024
#define LDS_ 140             // padded/swizzled smem row length (floats)

// Scratch: per-chunk D x D state matrices (exclusive-prefixed in place). 64 MiB.
__device__ float g_M[(size_t)NCHUNK_ * D_ * D_];

// Column placement swizzle: spreads 8-strided float4 reads across banks.
// pcol(j) = j + 4*(j/32). Preserves contiguity within any aligned 8-run.
__device__ __forceinline__ int pcol(int j) { return j + ((j >> 5) << 2); }

// ---------------------------------------------------------------------------
// Kernel A: M_g = K_g^T V_g  for each chunk g. Output 128x128 (d x n),
// reduction over t (chunk rows). Natural layouts: reduction index is the row.
// ---------------------------------------------------------------------------
__global__ void __launch_bounds__(256) kernA(const float* __restrict__ k,
                                             const float* __restrict__ v) {
    __shared__ float Ks[32 * LDS_];
    __shared__ float Vs[32 * LDS_];

    const int g = blockIdx.x;
    const float* kp = k + (size_t)g * C_ * D_;
    const float* vp = v + (size_t)g * C_ * D_;

    const int tid = threadIdx.x;
    const int tx = tid & 15, ty = tid >> 4;
    const int i0 = ty * 8, j0 = tx * 8;
    const int ip = pcol(i0), jp = pcol(j0);

    float acc[8][8] = {};

    for (int s = 0; s < 4; ++s) {
        __syncthreads();
        // Load 32-row slice of K and V (coalesced: each warp covers full rows)
#pragma unroll
        for (int it = 0; it < 4; ++it) {
            int idx = tid + it * 256;        // float4 index, 0..1023
            int row = idx >> 5;              // 0..31
            int c4  = (idx & 31) << 2;       // 0..124
            float4 kk4 = *(const float4*)(kp + (size_t)(s * 32 + row) * D_ + c4);
            float4 vv4 = *(const float4*)(vp + (size_t)(s * 32 + row) * D_ + c4);
            *(float4*)(Ks + row * LDS_ + pcol(c4)) = kk4;
            *(float4*)(Vs + row * LDS_ + pcol(c4)) = vv4;
        }
        __syncthreads();

#pragma unroll 4
        for (int kk = 0; kk < 32; ++kk) {
            float4 a0 = *(const float4*)(Ks + kk * LDS_ + ip);
            float4 a1 = *(const float4*)(Ks + kk * LDS_ + ip + 4);
            float4 b0 = *(const float4*)(Vs + kk * LDS_ + jp);
            float4 b1 = *(const float4*)(Vs + kk * LDS_ + jp + 4);
            float a[8] = {a0.x, a0.y, a0.z, a0.w, a1.x, a1.y, a1.z, a1.w};
            float b[8] = {b0.x, b0.y, b0.z, b0.w, b1.x, b1.y, b1.z, b1.w};
#pragma unroll
            for (int r = 0; r < 8; ++r)
#pragma unroll
                for (int c = 0; c < 8; ++c)
                    acc[r][c] += a[r] * b[c];
        }
    }

    float* mp = g_M + (size_t)g * D_ * D_;
#pragma unroll
    for (int r = 0; r < 8; ++r) {
        *(float4*)(mp + (size_t)(i0 + r) * D_ + j0) =
            make_float4(acc[r][0], acc[r][1], acc[r][2], acc[r][3]);
        *(float4*)(mp + (size_t)(i0 + r) * D_ + j0 + 4) =
            make_float4(acc[r][4], acc[r][5], acc[r][6], acc[r][7]);
    }
}

// ---------------------------------------------------------------------------
// Kernel B: in-place exclusive prefix over the 16 chunk states of each (b,h).
// Grid: 64 (bh) * 16 (element block). Each thread scans 4 elements (MLP=4).
// ---------------------------------------------------------------------------
__global__ void __launch_bounds__(256) kernB() {
    const int bh = blockIdx.x >> 4;
    const int eb = blockIdx.x & 15;
    const int e0 = eb * 1024 + threadIdx.x;
    const size_t base = (size_t)bh * NC_ * D_ * D_;

    float run[4] = {0.f, 0.f, 0.f, 0.f};
    for (int c = 0; c < NC_; ++c) {
        const size_t cb = base + (size_t)c * D_ * D_;
#pragma unroll
        for (int u = 0; u < 4; ++u) {
            size_t idx = cb + e0 + u * 256;
            float m = g_M[idx];
            g_M[idx] = run[u];
            run[u] += m;
        }
    }
}

// ---------------------------------------------------------------------------
// Kernel C: per chunk g:
//   scores = tril ⊙ (Q K^T)   (128x128, in smem)
//   O = scores @ V + Q @ S
// ---------------------------------------------------------------------------
__global__ void __launch_bounds__(256) kernC(const float* __restrict__ q,
                                             const float* __restrict__ k,
                                             const float* __restrict__ v,
                                             float* __restrict__ out) {
    extern __shared__ float sm[];
    float* Qt = sm;                    // Q transposed: [d][pcol(i)]
    float* Bb = sm + 128 * LDS_;       // K^T, then V, then S
    float* Ps = sm + 2 * 128 * LDS_;   // masked scores, natural [i][pcol(j)]

    const int g = blockIdx.x;
    const size_t base = (size_t)g * C_ * D_;

    const int tid = threadIdx.x;
    const int l = tid & 31, w = tid >> 5;
    const int tx = tid & 15, ty = tid >> 4;
    const int i0 = ty * 8, j0 = tx * 8;
    const int ip = pcol(i0), jp = pcol(j0);

    // ---- Load Q and K transposed into smem (reduction dim d becomes row) ----
    // Warp mapping: per iter, a warp covers 4 rows x 32 cols, 128B-coalesced.
#pragma unroll
    for (int it = 0; it < 16; ++it) {
        int lin = w * 16 + it;           // 0..127 (uniform per warp)
        int rowgrp = lin & 31;           // 0..31
        int colgrp = lin >> 5;           // 0..3
        int i = rowgrp * 4 + (l >> 3);
        int d = colgrp * 32 + ((l & 7) << 2);
        float4 qv = *(const float4*)(q + base + (size_t)i * D_ + d);
        float4 kv = *(const float4*)(k + base + (size_t)i * D_ + d);
        int pi = pcol(i);
        Qt[(d + 0) * LDS_ + pi] = qv.x;
        Qt[(d + 1) * LDS_ + pi] = qv.y;
        Qt[(d + 2) * LDS_ + pi] = qv.z;
        Qt[(d + 3) * LDS_ + pi] = qv.w;
        Bb[(d + 0) * LDS_ + pi] = kv.x;
        Bb[(d + 1) * LDS_ + pi] = kv.y;
        Bb[(d + 2) * LDS_ + pi] = kv.z;
        Bb[(d + 3) * LDS_ + pi] = kv.w;
    }
    __syncthreads();

    // ---- Phase 1: scores = Q K^T (reduction over d) ----
    float acc[8][8] = {};
#pragma unroll 4
    for (int d = 0; d < 128; ++d) {
        float4 a0 = *(const float4*)(Qt + d * LDS_ + ip);
        float4 a1 = *(const float4*)(Qt + d * LDS_ + ip + 4);
        float4 b0 = *(const float4*)(Bb + d * LDS_ + jp);
        float4 b1 = *(const float4*)(Bb + d * LDS_ + jp + 4);
        float a[8] = {a0.x, a0.y, a0.z, a0.w, a1.x, a1.y, a1.z, a1.w};
        float b[8] = {b0.x, b0.y, b0.z, b0.w, b1.x, b1.y, b1.z, b1.w};
#pragma unroll
        for (int r = 0; r < 8; ++r)
#pragma unroll
            for (int c = 0; c < 8; ++c)
                acc[r][c] += a[r] * b[c];
    }

    // ---- Mask (causal, inclusive diagonal) and store scores ----
#pragma unroll
    for (int r = 0; r < 8; ++r) {
        int i = i0 + r;
        float o[8];
#pragma unroll
        for (int c = 0; c < 8; ++c)
            o[c] = (j0 + c <= i) ? acc[r][c] : 0.f;
        *(float4*)(Ps + i * LDS_ + jp)     = make_float4(o[0], o[1], o[2], o[3]);
        *(float4*)(Ps + i * LDS_ + jp + 4) = make_float4(o[4], o[5], o[6], o[7]);
    }
    __syncthreads();

    // ---- Load V (natural) into Bb ----
#pragma unroll
    for (int it = 0; it < 16; ++it) {
        int idx = tid + it * 256;
        int row = idx >> 5;
        int c4  = (idx & 31) << 2;
        *(float4*)(Bb + row * LDS_ + pcol(c4)) =
            *(const float4*)(v + base + (size_t)row * D_ + c4);
    }
    __syncthreads();

    // ---- Phase 2a: O = scores @ V (reduction over j) ----
#pragma unroll
    for (int r = 0; r < 8; ++r)
#pragma unroll
        for (int c = 0; c < 8; ++c)
            acc[r][c] = 0.f;

#pragma unroll 2
    for (int j = 0; j < 128; ++j) {
        int pj = pcol(j);
        float a[8];
#pragma unroll
        for (int r = 0; r < 8; ++r)
            a[r] = Ps[(i0 + r) * LDS_ + pj];
        float4 b0 = *(const float4*)(Bb + j * LDS_ + jp);
        float4 b1 = *(const float4*)(Bb + j * LDS_ + jp + 4);
        float b[8] = {b0.x, b0.y, b0.z, b0.w, b1.x, b1.y, b1.z, b1.w};
#pragma unroll
        for (int r = 0; r < 8; ++r)
#pragma unroll
            for (int c = 0; c < 8; ++c)
                acc[r][c] += a[r] * b[c];
    }
    __syncthreads();

    // ---- Load S (exclusive prefix state) into Bb ----
    {
        const float* sp = g_M + (size_t)g * D_ * D_;
#pragma unroll
        for (int it = 0; it < 16; ++it) {
            int idx = tid + it * 256;
            int row = idx >> 5;
            int c4  = (idx & 31) << 2;
            *(float4*)(Bb + row * LDS_ + pcol(c4)) =
                *(const float4*)(sp + (size_t)row * D_ + c4);
        }
    }
    __syncthreads();

    // ---- Phase 2b: O += Q @ S (reduction over d) ----
#pragma unroll 4
    for (int d = 0; d < 128; ++d) {
        float4 a0 = *(const float4*)(Qt + d * LDS_ + ip);
        float4 a1 = *(const float4*)(Qt + d * LDS_ + ip + 4);
        float4 b0 = *(const float4*)(Bb + d * LDS_ + jp);
        float4 b1 = *(const float4*)(Bb + d * LDS_ + jp + 4);
        float a[8] = {a0.x, a0.y, a0.z, a0.w, a1.x, a1.y, a1.z, a1.w};
        float b[8] = {b0.x, b0.y, b0.z, b0.w, b1.x, b1.y, b1.z, b1.w};
#pragma unroll
        for (int r = 0; r < 8; ++r)
#pragma unroll
            for (int c = 0; c < 8; ++c)
                acc[r][c] += a[r] * b[c];
    }

    // ---- Store output ----
    float* op = out + base;
#pragma unroll
    for (int r = 0; r < 8; ++r) {
        *(float4*)(op + (size_t)(i0 + r) * D_ + j0) =
            make_float4(acc[r][0], acc[r][1], acc[r][2], acc[r][3]);
        *(float4*)(op + (size_t)(i0 + r) * D_ + j0 + 4) =
            make_float4(acc[r][4], acc[r][5], acc[r][6], acc[r][7]);
    }
}

// ---------------------------------------------------------------------------

extern "C" void kernel_launch(void* const* d_in, const int* in_sizes, int n_in,
                              void* d_out, int out_size) {
    const float* q = (const float*)d_in[0];
    const float* k = (const float*)d_in[1];
    const float* v = (const float*)d_in[2];
    float* out = (float*)d_out;

    const int smemC = 3 * 128 * LDS_ * (int)sizeof(float);  // 215040 B
    cudaFuncSetAttribute(kernC, cudaFuncAttributeMaxDynamicSharedMemorySize, smemC);

    kernA<<<NCHUNK_, 256>>>(k, v);
    kernB<<<BH_ * 16, 256>>>();
    kernC<<<NCHUNK_, 256, smemC>>>(q, k, v, out);
}

// round 3
// speedup vs baseline: 1.1445x; 1.1445x over previous
#include <cuda_runtime.h>
#include <cuda_bf16.h>
#include <stdint.h>

// Linear causal attention, chunked states, bf16-split mma.sync (legacy HMMA path;
// tcgen05 is unavailable: harness compiles for the non-'a' sm_103 target).
//   O_c = Q_c @ S_c + (tril ⊙ Q_c K_c^T) @ V_c,  S_c = sum_{c'<c} K_{c'}^T V_{c'}
// Each fp32 GEMM = Ah*Bh + Ah*Bl + Al*Bh in bf16 with fp32 accumulators.

#define NCHUNK 1024            // B*H*(T/128)
#define CE     16384           // 128*128
#define IMS    136             // bf16 elems per image row (pad 8 -> conflict-free ldmatrix)
#define IMRB   272             // bytes per image row
#define IMB    34816           // bytes per 128-row image
#define IMU4   2176            // uint4 per image

// Global scratch (~207 MB total).
__device__ float g_M[(size_t)NCHUNK * CE];
__device__ uint4 g_StH[(size_t)NCHUNK * IMU4];
__device__ uint4 g_StL[(size_t)NCHUNK * IMU4];
__device__ uint4 g_VtH[(size_t)NCHUNK * IMU4];
__device__ uint4 g_VtL[(size_t)NCHUNK * IMU4];

// ---------------- helpers ----------------
__device__ __forceinline__ uint32_t smem_u32(const void* p) {
    uint32_t a;
    asm("{ .reg .u64 t; cvta.to.shared.u64 t, %1; cvt.u32.u64 %0, t; }" : "=r"(a) : "l"(p));
    return a;
}
__device__ __forceinline__ void ldsm4(uint32_t a, uint32_t* r) {
    asm volatile("ldmatrix.sync.aligned.m8n8.x4.shared.b16 {%0,%1,%2,%3}, [%4];"
                 : "=r"(r[0]), "=r"(r[1]), "=r"(r[2]), "=r"(r[3]) : "r"(a));
}
__device__ __forceinline__ void mma16816(float* c, const uint32_t* a, uint32_t b0, uint32_t b1) {
    asm volatile("mma.sync.aligned.m16n8k16.row.col.f32.bf16.bf16.f32 "
                 "{%0,%1,%2,%3}, {%4,%5,%6,%7}, {%8,%9}, {%0,%1,%2,%3};"
                 : "+f"(c[0]), "+f"(c[1]), "+f"(c[2]), "+f"(c[3])
                 : "r"(a[0]), "r"(a[1]), "r"(a[2]), "r"(a[3]), "r"(b0), "r"(b1));
}
__device__ __forceinline__ void split2(float x0, float x1, uint32_t& hi, uint32_t& lo) {
    __nv_bfloat16 h0 = __float2bfloat16_rn(x0), h1 = __float2bfloat16_rn(x1);
    __nv_bfloat16 l0 = __float2bfloat16_rn(x0 - __bfloat162float(h0));
    __nv_bfloat16 l1 = __float2bfloat16_rn(x1 - __bfloat162float(h1));
    hi = ((uint32_t)__bfloat16_as_ushort(h1) << 16) | (uint32_t)__bfloat16_as_ushort(h0);
    lo = ((uint32_t)__bfloat16_as_ushort(l1) << 16) | (uint32_t)__bfloat16_as_ushort(l0);
}

// C(128x128) += [Ah|Ah|Al] x [Bh|Bl|Bh]^T over K=3*128. Warp tile 64x32.
// A images: rows = output row i, cols = k. B images: rows = output col j, cols = k.
__device__ __forceinline__ void gemm_chain(uint32_t AH, uint32_t AL, uint32_t BH, uint32_t BL,
                                           float (&acc)[4][4][4], int lane, int m0, int n0) {
    const uint32_t aof = (uint32_t)((lane & 15) * IMS + ((lane >> 4) << 3)) * 2u;
    const uint32_t bof = (uint32_t)(((lane & 7) + ((lane & 16) >> 1)) * IMS + (lane & 8)) * 2u;
    const uint32_t ab[3] = {AH, AH, AL};
    const uint32_t bb[3] = {BH, BL, BH};
#pragma unroll 1
    for (int term = 0; term < 3; ++term) {
        const uint32_t aA = ab[term] + aof + (uint32_t)m0 * IMRB;
        const uint32_t bA = bb[term] + bof + (uint32_t)n0 * IMRB;
#pragma unroll 2
        for (int kb = 0; kb < 8; ++kb) {
            uint32_t af[4][4], bf[2][4];
#pragma unroll
            for (int mf = 0; mf < 4; ++mf) ldsm4(aA + kb * 32 + mf * (16 * IMRB), af[mf]);
#pragma unroll
            for (int nh = 0; nh < 2; ++nh) ldsm4(bA + kb * 32 + nh * (16 * IMRB), bf[nh]);
#pragma unroll
            for (int mf = 0; mf < 4; ++mf)
#pragma unroll
                for (int nf = 0; nf < 4; ++nf)
                    mma16816(acc[mf][nf], af[mf],
                             bf[nf >> 1][(nf & 1) * 2], bf[nf >> 1][(nf & 1) * 2 + 1]);
        }
    }
}

// ---------------------------------------------------------------------------
// kernA: M_g = K_g^T V_g; builds Kt,Vt split images (transposed via fp32 stage),
// dumps Vt images to global for kernC, stores M fp32 for kernB.
// smem: KtH 0, KtL 34816, VtH 69632, VtL 104448, stage(128x132 f32) 139264. 206848 B.
// ---------------------------------------------------------------------------
#define A_SMEM 206848
__global__ void __launch_bounds__(256, 1) kernA(const float* __restrict__ k,
                                                const float* __restrict__ v) {
    extern __shared__ char sm[];
    const uint32_t sb = smem_u32(sm);
    float* stage = (float*)(sm + 139264);
    const int tid = threadIdx.x, lane = tid & 31, wid = tid >> 5;
    const int g = blockIdx.x;

#pragma unroll 1
    for (int pass = 0; pass < 2; ++pass) {
        const float* src = (pass ? v : k) + (size_t)g * CE;
        char* imh = sm + (pass ? 69632 : 0);
        char* iml = sm + (pass ? 104448 : 34816);
        __syncthreads();
#pragma unroll
        for (int it = 0; it < 16; ++it) {           // fp32 natural -> stage [t][d]
            int idx4 = it * 256 + tid, row = idx4 >> 5, c4 = (idx4 & 31) << 2;
            *(float4*)(stage + row * 132 + c4) = *(const float4*)(src + (size_t)row * 128 + c4);
        }
        __syncthreads();
#pragma unroll
        for (int it = 0; it < 16; ++it) {           // transpose + split -> image [d][t]
            int idx4 = it * 256 + tid, d = idx4 >> 5, t4 = (idx4 & 31) << 2;
            float x0 = stage[(t4 + 0) * 132 + d], x1 = stage[(t4 + 1) * 132 + d];
            float x2 = stage[(t4 + 2) * 132 + d], x3 = stage[(t4 + 3) * 132 + d];
            uint32_t h01, l01, h23, l23;
            split2(x0, x1, h01, l01);
            split2(x2, x3, h23, l23);
            *(uint2*)(imh + d * IMRB + t4 * 2) = make_uint2(h01, h23);
            *(uint2*)(iml + d * IMRB + t4 * 2) = make_uint2(l01, l23);
        }
    }
    __syncthreads();

    // Dump Vt images to global (read-only vs GEMM reads; no extra sync needed).
    {
        const uint4* s0 = (const uint4*)(sm + 69632);
        const uint4* s1 = (const uint4*)(sm + 104448);
        uint4* d0 = g_VtH + (size_t)g * IMU4;
        uint4* d1 = g_VtL + (size_t)g * IMU4;
        for (int i = tid; i < IMU4; i += 256) { d0[i] = s0[i]; d1[i] = s1[i]; }
    }

    float acc[4][4][4] = {};
    const int m0 = (wid & 1) * 64, n0 = (wid >> 1) * 32;
    gemm_chain(sb + 0, sb + 34816, sb + 69632, sb + 104448, acc, lane, m0, n0);

    float* mp = g_M + (size_t)g * CE;
#pragma unroll
    for (int mf = 0; mf < 4; ++mf)
#pragma unroll
        for (int nf = 0; nf < 4; ++nf) {
            int r = m0 + mf * 16 + (lane >> 2), c = n0 + nf * 8 + (lane & 3) * 2;
            *(float2*)(mp + (size_t)r * 128 + c)       = make_float2(acc[mf][nf][0], acc[mf][nf][1]);
            *(float2*)(mp + (size_t)(r + 8) * 128 + c) = make_float2(acc[mf][nf][2], acc[mf][nf][3]);
        }
}

// ---------------------------------------------------------------------------
// kernB: exclusive prefix over 16 chunk states per (b,h); emits S^T split images.
// smem: hi image @0, lo @34816. 69632 B.
// ---------------------------------------------------------------------------
__global__ void __launch_bounds__(256, 1) kernB() {
    extern __shared__ char sm[];
    const int tid = threadIdx.x;
    const int bh = blockIdx.x;
    float run[64];
#pragma unroll
    for (int u = 0; u < 64; ++u) run[u] = 0.f;

    for (int c = 0; c < 16; ++c) {
        const float* Mc = g_M + ((size_t)bh * 16 + c) * CE;
        __syncthreads();
#pragma unroll
        for (int u = 0; u < 64; ++u) {
            int idx = u * 256 + tid;           // M is [d][e]
            int d = idx >> 7, e = idx & 127;
            float x = run[u];
            __nv_bfloat16 h = __float2bfloat16_rn(x);
            __nv_bfloat16 l = __float2bfloat16_rn(x - __bfloat162float(h));
            *(unsigned short*)(sm + e * IMRB + d * 2)         = __bfloat16_as_ushort(h);
            *(unsigned short*)(sm + 34816 + e * IMRB + d * 2) = __bfloat16_as_ushort(l);
            run[u] += Mc[idx];
        }
        __syncthreads();
        uint4* dh = g_StH + ((size_t)bh * 16 + c) * IMU4;
        uint4* dl = g_StL + ((size_t)bh * 16 + c) * IMU4;
        for (int i = tid; i < IMU4; i += 256) {
            dh[i] = ((const uint4*)sm)[i];
            dl[i] = ((const uint4*)(sm + 34816))[i];
        }
    }
}

// ---------------------------------------------------------------------------
// kernC: O = Q@St + (tril ⊙ QK^T)@Vt.
// smem: QH 0, QL 34816, KH/PH 69632, KL/PL 104448, SH/VH 139264, SL/VL 174080. 208896 B.
// ---------------------------------------------------------------------------
#define C_SMEM 208896
__global__ void __launch_bounds__(256, 1) kernC(const float* __restrict__ q,
                                                const float* __restrict__ k,
                                                float* __restrict__ out) {
    extern __shared__ char sm[];
    const uint32_t sb = smem_u32(sm);
    const int tid = threadIdx.x, lane = tid & 31, wid = tid >> 5;
    const int g = blockIdx.x;
    const float* qp = q + (size_t)g * CE;
    const float* kp = k + (size_t)g * CE;

    // Convert Q, K (natural row-major, no transpose) into split images.
#pragma unroll
    for (int it = 0; it < 16; ++it) {
        int idx4 = it * 256 + tid, i = idx4 >> 5, c4 = (idx4 & 31) << 2;
        float4 a = *(const float4*)(qp + (size_t)i * 128 + c4);
        float4 b = *(const float4*)(kp + (size_t)i * 128 + c4);
        uint32_t h01, l01, h23, l23;
        split2(a.x, a.y, h01, l01); split2(a.z, a.w, h23, l23);
        *(uint2*)(sm + i * IMRB + c4 * 2)         = make_uint2(h01, h23);
        *(uint2*)(sm + 34816 + i * IMRB + c4 * 2) = make_uint2(l01, l23);
        split2(b.x, b.y, h01, l01); split2(b.z, b.w, h23, l23);
        *(uint2*)(sm + 69632 + i * IMRB + c4 * 2)  = make_uint2(h01, h23);
        *(uint2*)(sm + 104448 + i * IMRB + c4 * 2) = make_uint2(l01, l23);
    }
    // Copy S^T images from global.
    {
        const uint4* shh = g_StH + (size_t)g * IMU4;
        const uint4* sll = g_StL + (size_t)g * IMU4;
        for (int i = tid; i < IMU4; i += 256) {
            ((uint4*)(sm + 139264))[i] = shh[i];
            ((uint4*)(sm + 174080))[i] = sll[i];
        }
    }
    __syncthreads();

    const int m0 = (wid & 1) * 64, n0 = (wid >> 1) * 32;

    // O = Q @ St
    float acc2[4][4][4] = {};
    gemm_chain(sb + 0, sb + 34816, sb + 139264, sb + 174080, acc2, lane, m0, n0);
    __syncthreads();   // all warps done reading S region

    // Start async Vt -> S region; overlaps with the QK^T GEMM below.
    {
        const uint4* vh = g_VtH + (size_t)g * IMU4;
        const uint4* vl = g_VtL + (size_t)g * IMU4;
        for (int i = tid; i < IMU4; i += 256) {
            uint32_t d0 = sb + 139264 + i * 16, d1 = sb + 174080 + i * 16;
            asm volatile("cp.async.cg.shared.global [%0], [%1], 16;" :: "r"(d0), "l"(vh + i) : "memory");
            asm volatile("cp.async.cg.shared.global [%0], [%1], 16;" :: "r"(d1), "l"(vl + i) : "memory");
        }
        asm volatile("cp.async.commit_group;" ::: "memory");
    }

    // P = Q K^T
    float acc1[4][4][4] = {};
    gemm_chain(sb + 0, sb + 34816, sb + 69632, sb + 104448, acc1, lane, m0, n0);
    __syncthreads();   // all warps done reading K region before P overwrites it

    // Mask (causal) + split P into K's smem region.
#pragma unroll
    for (int mf = 0; mf < 4; ++mf)
#pragma unroll
        for (int nf = 0; nf < 4; ++nf) {
            int r = m0 + mf * 16 + (lane >> 2), c = n0 + nf * 8 + (lane & 3) * 2;
            float c0 = (c <= r) ? acc1[mf][nf][0] : 0.f;
            float c1 = (c + 1 <= r) ? acc1[mf][nf][1] : 0.f;
            float c2 = (c <= r + 8) ? acc1[mf][nf][2] : 0.f;
            float c3 = (c + 1 <= r + 8) ? acc1[mf][nf][3] : 0.f;
            uint32_t h, l;
            split2(c0, c1, h, l);
            *(uint32_t*)(sm + 69632 + r * IMRB + c * 2)  = h;
            *(uint32_t*)(sm + 104448 + r * IMRB + c * 2) = l;
            split2(c2, c3, h, l);
            *(uint32_t*)(sm + 69632 + (r + 8) * IMRB + c * 2)  = h;
            *(uint32_t*)(sm + 104448 + (r + 8) * IMRB + c * 2) = l;
        }
    asm volatile("cp.async.wait_group 0;" ::: "memory");
    __syncthreads();   // P visible, Vt landed

    // O += P @ Vt
    gemm_chain(sb + 69632, sb + 104448, sb + 139264, sb + 174080, acc2, lane, m0, n0);

    // Store O.
    float* op = out + (size_t)g * CE;
#pragma unroll
    for (int mf = 0; mf < 4; ++mf)
#pragma unroll
        for (int nf = 0; nf < 4; ++nf) {
            int r = m0 + mf * 16 + (lane >> 2), c = n0 + nf * 8 + (lane & 3) * 2;
            *(float2*)(op + (size_t)r * 128 + c)       = make_float2(acc2[mf][nf][0], acc2[mf][nf][1]);
            *(float2*)(op + (size_t)(r + 8) * 128 + c) = make_float2(acc2[mf][nf][2], acc2[mf][nf][3]);
        }
}

// ---------------------------------------------------------------------------

extern "C" void kernel_launch(void* const* d_in, const int* in_sizes, int n_in,
                              void* d_out, int out_size) {
    const float* q = (const float*)d_in[0];
    const float* k = (const float*)d_in[1];
    const float* v = (const float*)d_in[2];
    float* out = (float*)d_out;

    cudaFuncSetAttribute(kernA, cudaFuncAttributeMaxDynamicSharedMemorySize, A_SMEM);
    cudaFuncSetAttribute(kernB, cudaFuncAttributeMaxDynamicSharedMemorySize, 69632);
    cudaFuncSetAttribute(kernC, cudaFuncAttributeMaxDynamicSharedMemorySize, C_SMEM);

    kernA<<<NCHUNK, 256, A_SMEM>>>(k, v);
    kernB<<<64, 256, 69632>>>();
    kernC<<<NCHUNK, 256, C_SMEM>>>(q, k, out);
}

// round 4
// speedup vs baseline: 1.6380x; 1.4312x over previous
#include <cuda_runtime.h>
#include <cuda_bf16.h>
#include <stdint.h>

// Linear causal attention, chunked states, bf16-split mma.sync (legacy HMMA).
//   O_c = Q_c @ S_c + (tril ⊙ Q_c K_c^T) @ V_c,  S_c = sum_{c'<c} K_{c'}^T V_{c'}
// fp32 GEMM = Ah*Bh + Ah*Bl + Al*Bh in bf16, fp32 accum.

#define NCHUNK 1024
#define CE     16384
#define IMS    136             // bf16 elems per image row
#define IMRB   272             // bytes per image row
#define IMU4   2176            // uint4 per 128-row image

__device__ float g_M[(size_t)NCHUNK * CE];
__device__ uint4 g_StH[(size_t)NCHUNK * IMU4];
__device__ uint4 g_StL[(size_t)NCHUNK * IMU4];
__device__ uint4 g_VtH[(size_t)NCHUNK * IMU4];
__device__ uint4 g_VtL[(size_t)NCHUNK * IMU4];

// ---------------- helpers ----------------
__device__ __forceinline__ uint32_t smem_u32(const void* p) {
    uint32_t a;
    asm("{ .reg .u64 t; cvta.to.shared.u64 t, %1; cvt.u32.u64 %0, t; }" : "=r"(a) : "l"(p));
    return a;
}
__device__ __forceinline__ void ldsm4(uint32_t a, uint32_t* r) {
    asm volatile("ldmatrix.sync.aligned.m8n8.x4.shared.b16 {%0,%1,%2,%3}, [%4];"
                 : "=r"(r[0]), "=r"(r[1]), "=r"(r[2]), "=r"(r[3]) : "r"(a));
}
__device__ __forceinline__ void mma16816(float* c, const uint32_t* a, uint32_t b0, uint32_t b1) {
    asm volatile("mma.sync.aligned.m16n8k16.row.col.f32.bf16.bf16.f32 "
                 "{%0,%1,%2,%3}, {%4,%5,%6,%7}, {%8,%9}, {%0,%1,%2,%3};"
                 : "+f"(c[0]), "+f"(c[1]), "+f"(c[2]), "+f"(c[3])
                 : "r"(a[0]), "r"(a[1]), "r"(a[2]), "r"(a[3]), "r"(b0), "r"(b1));
}
__device__ __forceinline__ void split2(float x0, float x1, uint32_t& hi, uint32_t& lo) {
    __nv_bfloat16 h0 = __float2bfloat16_rn(x0), h1 = __float2bfloat16_rn(x1);
    __nv_bfloat16 l0 = __float2bfloat16_rn(x0 - __bfloat162float(h0));
    __nv_bfloat16 l1 = __float2bfloat16_rn(x1 - __bfloat162float(h1));
    hi = ((uint32_t)__bfloat16_as_ushort(h1) << 16) | (uint32_t)__bfloat16_as_ushort(h0);
    lo = ((uint32_t)__bfloat16_as_ushort(l1) << 16) | (uint32_t)__bfloat16_as_ushort(l0);
}

// C(32x32 warp tile) += [Ah|Ah|Al] x [Bh|Bl|Bh]^T, K=128. Merged terms:
// per k-block load Ah/Al/Bh/Bl fragments once, issue 3 mma terms.
__device__ __forceinline__ void gemm_tile(uint32_t AH, uint32_t AL, uint32_t BH, uint32_t BL,
                                          float (&acc)[2][4][4], int lane, int m0, int n0) {
    const uint32_t aof = (uint32_t)((lane & 15) * IMS + ((lane >> 4) << 3)) * 2u;
    const uint32_t bof = (uint32_t)(((lane & 7) + ((lane & 16) >> 1)) * IMS + (lane & 8)) * 2u;
    const uint32_t aH = AH + aof + (uint32_t)m0 * IMRB;
    const uint32_t aL = AL + aof + (uint32_t)m0 * IMRB;
    const uint32_t bH = BH + bof + (uint32_t)n0 * IMRB;
    const uint32_t bL = BL + bof + (uint32_t)n0 * IMRB;
#pragma unroll
    for (int kb = 0; kb < 8; ++kb) {
        uint32_t ah[2][4], al[2][4], bh[2][4], bl[2][4];
#pragma unroll
        for (int mf = 0; mf < 2; ++mf) {
            ldsm4(aH + kb * 32 + mf * (16 * IMRB), ah[mf]);
            ldsm4(aL + kb * 32 + mf * (16 * IMRB), al[mf]);
        }
#pragma unroll
        for (int nh = 0; nh < 2; ++nh) {
            ldsm4(bH + kb * 32 + nh * (16 * IMRB), bh[nh]);
            ldsm4(bL + kb * 32 + nh * (16 * IMRB), bl[nh]);
        }
#pragma unroll
        for (int mf = 0; mf < 2; ++mf)
#pragma unroll
            for (int nf = 0; nf < 4; ++nf) {
                uint32_t b0h = bh[nf >> 1][(nf & 1) * 2], b1h = bh[nf >> 1][(nf & 1) * 2 + 1];
                uint32_t b0l = bl[nf >> 1][(nf & 1) * 2], b1l = bl[nf >> 1][(nf & 1) * 2 + 1];
                mma16816(acc[mf][nf], ah[mf], b0h, b1h);
                mma16816(acc[mf][nf], ah[mf], b0l, b1l);
                mma16816(acc[mf][nf], al[mf], b0h, b1h);
            }
    }
}

// ---------------------------------------------------------------------------
// kernA: M_g = K_g^T V_g. Builds Kt,Vt split images via fp32 stage (pitch 129,
// scalar 4-way-conflict transpose), dumps Vt to global, GEMM, stores M fp32.
// smem: KtH 0, KtL 34816, VtH 69632, VtL 104448, stage 139264 (+66048) = 205312.
// ---------------------------------------------------------------------------
#define A_STG  139264
#define A_SMEM 205312
__global__ void __launch_bounds__(512, 1) kernA(const float* __restrict__ k,
                                                const float* __restrict__ v) {
    extern __shared__ char sm[];
    const uint32_t sb = smem_u32(sm);
    float* stage = (float*)(sm + A_STG);
    const int tid = threadIdx.x, lane = tid & 31, wid = tid >> 5;
    const int g = blockIdx.x;

#pragma unroll 1
    for (int pass = 0; pass < 2; ++pass) {
        const float* src = (pass ? v : k) + (size_t)g * CE;
        char* imh = sm + (pass ? 69632 : 0);
        char* iml = sm + (pass ? 104448 : 34816);
        __syncthreads();
#pragma unroll
        for (int it = 0; it < 8; ++it) {            // gmem [t][d] -> stage (pitch 129)
            int idx4 = it * 512 + tid, t = idx4 >> 5, d4 = (idx4 & 31) << 2;
            float4 x = *(const float4*)(src + (size_t)t * 128 + d4);
            float* sp = stage + t * 129 + d4;
            sp[0] = x.x; sp[1] = x.y; sp[2] = x.z; sp[3] = x.w;
        }
        __syncthreads();
#pragma unroll
        for (int it = 0; it < 8; ++it) {            // transpose + split -> image [d][t]
            int idx4 = it * 512 + tid, d = idx4 >> 5, t4 = (idx4 & 31) << 2;
            float x0 = stage[(t4 + 0) * 129 + d], x1 = stage[(t4 + 1) * 129 + d];
            float x2 = stage[(t4 + 2) * 129 + d], x3 = stage[(t4 + 3) * 129 + d];
            uint32_t h01, l01, h23, l23;
            split2(x0, x1, h01, l01);
            split2(x2, x3, h23, l23);
            *(uint2*)(imh + d * IMRB + t4 * 2) = make_uint2(h01, h23);
            *(uint2*)(iml + d * IMRB + t4 * 2) = make_uint2(l01, l23);
        }
    }
    __syncthreads();

    // Dump Vt images to global (read-only vs GEMM reads below).
    {
        const uint4* s0 = (const uint4*)(sm + 69632);
        const uint4* s1 = (const uint4*)(sm + 104448);
        uint4* d0 = g_VtH + (size_t)g * IMU4;
        uint4* d1 = g_VtL + (size_t)g * IMU4;
        for (int i = tid; i < IMU4; i += 512) { d0[i] = s0[i]; d1[i] = s1[i]; }
    }

    float acc[2][4][4] = {};
    const int m0 = (wid & 3) * 32, n0 = (wid >> 2) * 32;
    gemm_tile(sb + 0, sb + 34816, sb + 69632, sb + 104448, acc, lane, m0, n0);

    float* mp = g_M + (size_t)g * CE;
#pragma unroll
    for (int mf = 0; mf < 2; ++mf)
#pragma unroll
        for (int nf = 0; nf < 4; ++nf) {
            int r = m0 + mf * 16 + (lane >> 2), c = n0 + nf * 8 + (lane & 3) * 2;
            *(float2*)(mp + (size_t)r * 128 + c)       = make_float2(acc[mf][nf][0], acc[mf][nf][1]);
            *(float2*)(mp + (size_t)(r + 8) * 128 + c) = make_float2(acc[mf][nf][2], acc[mf][nf][3]);
        }
}

// ---------------------------------------------------------------------------
// kernB: exclusive prefix over 16 chunk states per (b,h); emits S^T split
// images. Grid 512 = 64 bh x 8 element-slices (16 image rows each).
// ---------------------------------------------------------------------------
__global__ void __launch_bounds__(256, 1) kernB() {
    __shared__ char sm[8704];                  // hi slice @0 (4352), lo @4352
    const int tid = threadIdx.x;
    const int bh = blockIdx.x >> 3, eb = blockIdx.x & 7;
    float run[8];
#pragma unroll
    for (int u = 0; u < 8; ++u) run[u] = 0.f;

    for (int c = 0; c < 16; ++c) {
        const float* Mc = g_M + ((size_t)bh * 16 + c) * CE;
        __syncthreads();
#pragma unroll
        for (int u = 0; u < 8; ++u) {
            int idx = u * 256 + tid;            // slice elem: d = idx>>4, e_local = idx&15
            int d = idx >> 4, el = idx & 15;
            float x = run[u];
            __nv_bfloat16 h = __float2bfloat16_rn(x);
            __nv_bfloat16 l = __float2bfloat16_rn(x - __bfloat162float(h));
            *(unsigned short*)(sm + el * IMRB + d * 2)        = __bfloat16_as_ushort(h);
            *(unsigned short*)(sm + 4352 + el * IMRB + d * 2) = __bfloat16_as_ushort(l);
            run[u] += Mc[(size_t)d * 128 + eb * 16 + el];
        }
        __syncthreads();
        uint4* dh = g_StH + ((size_t)bh * 16 + c) * IMU4 + eb * 272;
        uint4* dl = g_StL + ((size_t)bh * 16 + c) * IMU4 + eb * 272;
        for (int i = tid; i < 272; i += 256) {
            dh[i] = ((const uint4*)sm)[i];
            dl[i] = ((const uint4*)(sm + 4352))[i];
        }
    }
}

// ---------------------------------------------------------------------------
// kernC: O = Q@St + (tril ⊙ QK^T)@Vt.
// smem: QH 0, QL 34816, KH/PH 69632, KL/PL 104448, SH/VH 139264, SL/VL 174080.
// ---------------------------------------------------------------------------
#define C_SMEM 208896
__global__ void __launch_bounds__(512, 1) kernC(const float* __restrict__ q,
                                                const float* __restrict__ k,
                                                float* __restrict__ out) {
    extern __shared__ char sm[];
    const uint32_t sb = smem_u32(sm);
    const int tid = threadIdx.x, lane = tid & 31, wid = tid >> 5;
    const int g = blockIdx.x;
    const float* qp = q + (size_t)g * CE;
    const float* kp = k + (size_t)g * CE;

    // Async St load overlaps with Q/K conversion.
    {
        const uint4* shh = g_StH + (size_t)g * IMU4;
        const uint4* sll = g_StL + (size_t)g * IMU4;
        for (int i = tid; i < IMU4; i += 512) {
            uint32_t d0 = sb + 139264 + i * 16, d1 = sb + 174080 + i * 16;
            asm volatile("cp.async.cg.shared.global [%0], [%1], 16;" :: "r"(d0), "l"(shh + i) : "memory");
            asm volatile("cp.async.cg.shared.global [%0], [%1], 16;" :: "r"(d1), "l"(sll + i) : "memory");
        }
        asm volatile("cp.async.commit_group;" ::: "memory");
    }
    // Convert Q, K (natural, no transpose) into split images.
#pragma unroll
    for (int it = 0; it < 8; ++it) {
        int idx4 = it * 512 + tid, i = idx4 >> 5, c4 = (idx4 & 31) << 2;
        float4 a = *(const float4*)(qp + (size_t)i * 128 + c4);
        float4 b = *(const float4*)(kp + (size_t)i * 128 + c4);
        uint32_t h01, l01, h23, l23;
        split2(a.x, a.y, h01, l01); split2(a.z, a.w, h23, l23);
        *(uint2*)(sm + i * IMRB + c4 * 2)         = make_uint2(h01, h23);
        *(uint2*)(sm + 34816 + i * IMRB + c4 * 2) = make_uint2(l01, l23);
        split2(b.x, b.y, h01, l01); split2(b.z, b.w, h23, l23);
        *(uint2*)(sm + 69632 + i * IMRB + c4 * 2)  = make_uint2(h01, h23);
        *(uint2*)(sm + 104448 + i * IMRB + c4 * 2) = make_uint2(l01, l23);
    }
    asm volatile("cp.async.wait_group 0;" ::: "memory");
    __syncthreads();

    const int m0 = (wid & 3) * 32, n0 = (wid >> 2) * 32;

    // O = Q @ St
    float acc2[2][4][4] = {};
    gemm_tile(sb + 0, sb + 34816, sb + 139264, sb + 174080, acc2, lane, m0, n0);
    __syncthreads();     // all warps done reading St region

    // Async Vt -> St region; overlaps with QK^T below.
    {
        const uint4* vh = g_VtH + (size_t)g * IMU4;
        const uint4* vl = g_VtL + (size_t)g * IMU4;
        for (int i = tid; i < IMU4; i += 512) {
            uint32_t d0 = sb + 139264 + i * 16, d1 = sb + 174080 + i * 16;
            asm volatile("cp.async.cg.shared.global [%0], [%1], 16;" :: "r"(d0), "l"(vh + i) : "memory");
            asm volatile("cp.async.cg.shared.global [%0], [%1], 16;" :: "r"(d1), "l"(vl + i) : "memory");
        }
        asm volatile("cp.async.commit_group;" ::: "memory");
    }

    // P = Q K^T
    float acc1[2][4][4] = {};
    gemm_tile(sb + 0, sb + 34816, sb + 69632, sb + 104448, acc1, lane, m0, n0);
    __syncthreads();     // all warps done reading K region

    // Mask (causal) + split P into K's region.
#pragma unroll
    for (int mf = 0; mf < 2; ++mf)
#pragma unroll
        for (int nf = 0; nf < 4; ++nf) {
            int r = m0 + mf * 16 + (lane >> 2), c = n0 + nf * 8 + (lane & 3) * 2;
            float c0 = (c <= r) ? acc1[mf][nf][0] : 0.f;
            float c1 = (c + 1 <= r) ? acc1[mf][nf][1] : 0.f;
            float c2 = (c <= r + 8) ? acc1[mf][nf][2] : 0.f;
            float c3 = (c + 1 <= r + 8) ? acc1[mf][nf][3] : 0.f;
            uint32_t h, l;
            split2(c0, c1, h, l);
            *(uint32_t*)(sm + 69632 + r * IMRB + c * 2)  = h;
            *(uint32_t*)(sm + 104448 + r * IMRB + c * 2) = l;
            split2(c2, c3, h, l);
            *(uint32_t*)(sm + 69632 + (r + 8) * IMRB + c * 2)  = h;
            *(uint32_t*)(sm + 104448 + (r + 8) * IMRB + c * 2) = l;
        }
    asm volatile("cp.async.wait_group 0;" ::: "memory");
    __syncthreads();     // P visible, Vt landed

    // O += P @ Vt
    gemm_tile(sb + 69632, sb + 104448, sb + 139264, sb + 174080, acc2, lane, m0, n0);

    float* op = out + (size_t)g * CE;
#pragma unroll
    for (int mf = 0; mf < 2; ++mf)
#pragma unroll
        for (int nf = 0; nf < 4; ++nf) {
            int r = m0 + mf * 16 + (lane >> 2), c = n0 + nf * 8 + (lane & 3) * 2;
            *(float2*)(op + (size_t)r * 128 + c)       = make_float2(acc2[mf][nf][0], acc2[mf][nf][1]);
            *(float2*)(op + (size_t)(r + 8) * 128 + c) = make_float2(acc2[mf][nf][2], acc2[mf][nf][3]);
        }
}

// ---------------------------------------------------------------------------

extern "C" void kernel_launch(void* const* d_in, const int* in_sizes, int n_in,
                              void* d_out, int out_size) {
    const float* q = (const float*)d_in[0];
    const float* k = (const float*)d_in[1];
    const float* v = (const float*)d_in[2];
    float* out = (float*)d_out;

    cudaFuncSetAttribute(kernA, cudaFuncAttributeMaxDynamicSharedMemorySize, A_SMEM);
    cudaFuncSetAttribute(kernC, cudaFuncAttributeMaxDynamicSharedMemorySize, C_SMEM);

    kernA<<<NCHUNK, 512, A_SMEM>>>(k, v);
    kernB<<<512, 256>>>();
    kernC<<<NCHUNK, 512, C_SMEM>>>(q, k, out);
}

// round 5
// speedup vs baseline: 1.7581x; 1.0733x over previous
#include <cuda_runtime.h>
#include <cuda_bf16.h>
#include <stdint.h>

// Linear causal attention, chunked states, bf16-split mma.sync.
//   O_c = Q_c @ S_c + (tril ⊙ Q_c K_c^T) @ V_c,  S_c = sum_{c'<c} K_{c'}^T V_{c'}
// fp32 GEMM = Ah*Bh + Ah*Bl + Al*Bh in bf16, fp32 accum. All operands kept in
// natural [t][d] layout; transposed fragments come from ldmatrix.trans.

#define NCHUNK 1024
#define CE     16384
#define IMS    136             // bf16 elems per image row
#define IMRB   272             // bytes per image row
#define IMU4   2176            // uint4 per 128-row image

__device__ float g_M[(size_t)NCHUNK * CE];        // K^T V per chunk, fp32
__device__ uint4 g_SH[(size_t)NCHUNK * IMU4];     // exclusive-prefix S, natural split images
__device__ uint4 g_SL[(size_t)NCHUNK * IMU4];

// ---------------- helpers ----------------
__device__ __forceinline__ uint32_t smem_u32(const void* p) {
    uint32_t a;
    asm("{ .reg .u64 t; cvta.to.shared.u64 t, %1; cvt.u32.u64 %0, t; }" : "=r"(a) : "l"(p));
    return a;
}
__device__ __forceinline__ void ldsm4(uint32_t a, uint32_t* r) {
    asm volatile("ldmatrix.sync.aligned.m8n8.x4.shared.b16 {%0,%1,%2,%3}, [%4];"
                 : "=r"(r[0]), "=r"(r[1]), "=r"(r[2]), "=r"(r[3]) : "r"(a));
}
__device__ __forceinline__ void ldsm4t(uint32_t a, uint32_t* r) {
    asm volatile("ldmatrix.sync.aligned.m8n8.x4.trans.shared.b16 {%0,%1,%2,%3}, [%4];"
                 : "=r"(r[0]), "=r"(r[1]), "=r"(r[2]), "=r"(r[3]) : "r"(a));
}
__device__ __forceinline__ void mma16816(float* c, const uint32_t* a, uint32_t b0, uint32_t b1) {
    asm volatile("mma.sync.aligned.m16n8k16.row.col.f32.bf16.bf16.f32 "
                 "{%0,%1,%2,%3}, {%4,%5,%6,%7}, {%8,%9}, {%0,%1,%2,%3};"
                 : "+f"(c[0]), "+f"(c[1]), "+f"(c[2]), "+f"(c[3])
                 : "r"(a[0]), "r"(a[1]), "r"(a[2]), "r"(a[3]), "r"(b0), "r"(b1));
}
__device__ __forceinline__ void split2(float x0, float x1, uint32_t& hi, uint32_t& lo) {
    __nv_bfloat16 h0 = __float2bfloat16_rn(x0), h1 = __float2bfloat16_rn(x1);
    __nv_bfloat16 l0 = __float2bfloat16_rn(x0 - __bfloat162float(h0));
    __nv_bfloat16 l1 = __float2bfloat16_rn(x1 - __bfloat162float(h1));
    hi = ((uint32_t)__bfloat16_as_ushort(h1) << 16) | (uint32_t)__bfloat16_as_ushort(h0);
    lo = ((uint32_t)__bfloat16_as_ushort(l1) << 16) | (uint32_t)__bfloat16_as_ushort(l0);
}

// C(32x32 warp tile) += [Ah|Ah|Al] x [Bh|Bl|Bh], K=128.
// TA: A image holds A^T ([k][m], natural) -> trans fragments.
// TB: B image holds B^T-source ([k][n], natural) -> trans fragments.
// Register order after ldmatrix matches the non-trans case, so mma use is identical.
template <bool TA, bool TB>
__device__ __forceinline__ void gemm_tile(uint32_t AH, uint32_t AL, uint32_t BH, uint32_t BL,
                                          float (&acc)[2][4][4], int lane, int m0, int n0) {
    const uint32_t a_lane = TA
        ? (uint32_t)(((lane & 7) + ((lane >> 4) << 3)) * IMRB + ((((lane >> 3) & 1) << 3) << 1))
        : (uint32_t)((lane & 15) * IMRB + (((lane >> 4) << 3) << 1));
    const uint32_t b_lane = TB
        ? (uint32_t)(((lane & 7) + (((lane >> 3) & 1) << 3)) * IMRB + ((((lane >> 4) & 1) << 3) << 1))
        : (uint32_t)(((lane & 7) + ((lane & 16) >> 1)) * IMRB + ((lane & 8) << 1));
    const uint32_t aH = AH + a_lane + (TA ? (uint32_t)m0 * 2 : (uint32_t)m0 * IMRB);
    const uint32_t aL = AL + a_lane + (TA ? (uint32_t)m0 * 2 : (uint32_t)m0 * IMRB);
    const uint32_t bH = BH + b_lane + (TB ? (uint32_t)n0 * 2 : (uint32_t)n0 * IMRB);
    const uint32_t bL = BL + b_lane + (TB ? (uint32_t)n0 * 2 : (uint32_t)n0 * IMRB);
    const uint32_t a_kb = TA ? 16 * IMRB : 32;
    const uint32_t a_mf = TA ? 32 : 16 * IMRB;
    const uint32_t b_kb = TB ? 16 * IMRB : 32;
    const uint32_t b_nh = TB ? 32 : 16 * IMRB;
#pragma unroll
    for (int kb = 0; kb < 8; ++kb) {
        uint32_t ah[2][4], al[2][4], bh[2][4], bl[2][4];
#pragma unroll
        for (int mf = 0; mf < 2; ++mf) {
            if (TA) { ldsm4t(aH + kb * a_kb + mf * a_mf, ah[mf]); ldsm4t(aL + kb * a_kb + mf * a_mf, al[mf]); }
            else    { ldsm4 (aH + kb * a_kb + mf * a_mf, ah[mf]); ldsm4 (aL + kb * a_kb + mf * a_mf, al[mf]); }
        }
#pragma unroll
        for (int nh = 0; nh < 2; ++nh) {
            if (TB) { ldsm4t(bH + kb * b_kb + nh * b_nh, bh[nh]); ldsm4t(bL + kb * b_kb + nh * b_nh, bl[nh]); }
            else    { ldsm4 (bH + kb * b_kb + nh * b_nh, bh[nh]); ldsm4 (bL + kb * b_kb + nh * b_nh, bl[nh]); }
        }
#pragma unroll
        for (int mf = 0; mf < 2; ++mf)
#pragma unroll
            for (int nf = 0; nf < 4; ++nf) {
                uint32_t b0h = bh[nf >> 1][(nf & 1) * 2], b1h = bh[nf >> 1][(nf & 1) * 2 + 1];
                uint32_t b0l = bl[nf >> 1][(nf & 1) * 2], b1l = bl[nf >> 1][(nf & 1) * 2 + 1];
                mma16816(acc[mf][nf], ah[mf], b0h, b1h);
                mma16816(acc[mf][nf], ah[mf], b0l, b1l);
                mma16816(acc[mf][nf], al[mf], b0h, b1h);
            }
    }
}

// ---------------------------------------------------------------------------
// kernA: M_g = K_g^T V_g. Natural split images of K and V; trans fragments.
// smem: KH 0, KL 34816, VH 69632, VL 104448. 139264 B.
// ---------------------------------------------------------------------------
#define A_SMEM 139264
__global__ void __launch_bounds__(512, 1) kernA(const float* __restrict__ k,
                                                const float* __restrict__ v) {
    extern __shared__ char sm[];
    const uint32_t sb = smem_u32(sm);
    const int tid = threadIdx.x, lane = tid & 31, wid = tid >> 5;
    const int g = blockIdx.x;
    const float* kp = k + (size_t)g * CE;
    const float* vp = v + (size_t)g * CE;

#pragma unroll
    for (int it = 0; it < 8; ++it) {
        int idx4 = it * 512 + tid, t = idx4 >> 5, c4 = (idx4 & 31) << 2;
        float4 a = *(const float4*)(kp + (size_t)t * 128 + c4);
        float4 b = *(const float4*)(vp + (size_t)t * 128 + c4);
        uint32_t h01, l01, h23, l23;
        split2(a.x, a.y, h01, l01); split2(a.z, a.w, h23, l23);
        *(uint2*)(sm + t * IMRB + c4 * 2)         = make_uint2(h01, h23);
        *(uint2*)(sm + 34816 + t * IMRB + c4 * 2) = make_uint2(l01, l23);
        split2(b.x, b.y, h01, l01); split2(b.z, b.w, h23, l23);
        *(uint2*)(sm + 69632 + t * IMRB + c4 * 2)  = make_uint2(h01, h23);
        *(uint2*)(sm + 104448 + t * IMRB + c4 * 2) = make_uint2(l01, l23);
    }
    __syncthreads();

    // M[d_k][d_out]: A = K^T (trans of natural K), B side from natural V (trans).
    float acc[2][4][4] = {};
    const int m0 = (wid & 3) * 32, n0 = (wid >> 2) * 32;
    gemm_tile<true, true>(sb + 0, sb + 34816, sb + 69632, sb + 104448, acc, lane, m0, n0);

    float* mp = g_M + (size_t)g * CE;
#pragma unroll
    for (int mf = 0; mf < 2; ++mf)
#pragma unroll
        for (int nf = 0; nf < 4; ++nf) {
            int r = m0 + mf * 16 + (lane >> 2), c = n0 + nf * 8 + (lane & 3) * 2;
            *(float2*)(mp + (size_t)r * 128 + c)       = make_float2(acc[mf][nf][0], acc[mf][nf][1]);
            *(float2*)(mp + (size_t)(r + 8) * 128 + c) = make_float2(acc[mf][nf][2], acc[mf][nf][3]);
        }
}

// ---------------------------------------------------------------------------
// kernB: exclusive prefix over 16 chunk states per (b,h); natural split images.
// Grid 512 = 64 bh x 8 row-slices (16 d_k rows each).
// ---------------------------------------------------------------------------
__global__ void __launch_bounds__(256, 1) kernB() {
    __shared__ char sm[8704];                  // hi slice @0 (4352 B), lo @4352
    const int tid = threadIdx.x;
    const int bh = blockIdx.x >> 3, eb = blockIdx.x & 7;
    float run[8];
#pragma unroll
    for (int u = 0; u < 8; ++u) run[u] = 0.f;

    for (int c = 0; c < 16; ++c) {
        const float* Mc = g_M + ((size_t)bh * 16 + c) * CE;
        __syncthreads();
#pragma unroll
        for (int u = 0; u < 8; ++u) {
            int idx = u * 256 + tid;            // slice elem: dl = idx>>7 (row), e = idx&127
            int dl = idx >> 7, e = idx & 127;
            float x = run[u];
            __nv_bfloat16 h = __float2bfloat16_rn(x);
            __nv_bfloat16 l = __float2bfloat16_rn(x - __bfloat162float(h));
            *(unsigned short*)(sm + dl * IMRB + e * 2)        = __bfloat16_as_ushort(h);
            *(unsigned short*)(sm + 4352 + dl * IMRB + e * 2) = __bfloat16_as_ushort(l);
            run[u] += Mc[(size_t)(eb * 16 + dl) * 128 + e];
        }
        __syncthreads();
        uint4* dh = g_SH + ((size_t)bh * 16 + c) * IMU4 + eb * 272;
        uint4* dl4 = g_SL + ((size_t)bh * 16 + c) * IMU4 + eb * 272;
        for (int i = tid; i < 272; i += 256) {
            dh[i]  = ((const uint4*)sm)[i];
            dl4[i] = ((const uint4*)(sm + 4352))[i];
        }
    }
}

// ---------------------------------------------------------------------------
// kernC: O = Q@S + (tril ⊙ QK^T)@V. All natural images.
// smem: QH 0 (->P), QL 34816, KH 69632, KL 104448, SH 139264 (->V), SL 174080.
// ---------------------------------------------------------------------------
#define C_SMEM 208896
__global__ void __launch_bounds__(512, 1) kernC(const float* __restrict__ q,
                                                const float* __restrict__ k,
                                                const float* __restrict__ v,
                                                float* __restrict__ out) {
    extern __shared__ char sm[];
    const uint32_t sb = smem_u32(sm);
    const int tid = threadIdx.x, lane = tid & 31, wid = tid >> 5;
    const int g = blockIdx.x;
    const float* qp = q + (size_t)g * CE;
    const float* kp = k + (size_t)g * CE;
    const float* vp = v + (size_t)g * CE;

    // Async S images overlap the Q/K conversion.
    {
        const uint4* shh = g_SH + (size_t)g * IMU4;
        const uint4* sll = g_SL + (size_t)g * IMU4;
        for (int i = tid; i < IMU4; i += 512) {
            uint32_t d0 = sb + 139264 + i * 16, d1 = sb + 174080 + i * 16;
            asm volatile("cp.async.cg.shared.global [%0], [%1], 16;" :: "r"(d0), "l"(shh + i) : "memory");
            asm volatile("cp.async.cg.shared.global [%0], [%1], 16;" :: "r"(d1), "l"(sll + i) : "memory");
        }
        asm volatile("cp.async.commit_group;" ::: "memory");
    }
#pragma unroll
    for (int it = 0; it < 8; ++it) {
        int idx4 = it * 512 + tid, i = idx4 >> 5, c4 = (idx4 & 31) << 2;
        float4 a = *(const float4*)(qp + (size_t)i * 128 + c4);
        float4 b = *(const float4*)(kp + (size_t)i * 128 + c4);
        uint32_t h01, l01, h23, l23;
        split2(a.x, a.y, h01, l01); split2(a.z, a.w, h23, l23);
        *(uint2*)(sm + i * IMRB + c4 * 2)         = make_uint2(h01, h23);
        *(uint2*)(sm + 34816 + i * IMRB + c4 * 2) = make_uint2(l01, l23);
        split2(b.x, b.y, h01, l01); split2(b.z, b.w, h23, l23);
        *(uint2*)(sm + 69632 + i * IMRB + c4 * 2)  = make_uint2(h01, h23);
        *(uint2*)(sm + 104448 + i * IMRB + c4 * 2) = make_uint2(l01, l23);
    }
    asm volatile("cp.async.wait_group 0;" ::: "memory");
    __syncthreads();

    const int m0 = (wid & 3) * 32, n0 = (wid >> 2) * 32;

    // O1 = Q @ S  (S natural [d_k][d_out] -> trans B), then P = Q K^T (both natural).
    float acc2[2][4][4] = {};
    gemm_tile<false, true>(sb + 0, sb + 34816, sb + 139264, sb + 174080, acc2, lane, m0, n0);
    float acc1[2][4][4] = {};
    gemm_tile<false, false>(sb + 0, sb + 34816, sb + 69632, sb + 104448, acc1, lane, m0, n0);
    __syncthreads();     // Q, S regions now dead

    // Mask + split P into the Q region; convert V into the S region.
#pragma unroll
    for (int mf = 0; mf < 2; ++mf)
#pragma unroll
        for (int nf = 0; nf < 4; ++nf) {
            int r = m0 + mf * 16 + (lane >> 2), c = n0 + nf * 8 + (lane & 3) * 2;
            float c0 = (c <= r) ? acc1[mf][nf][0] : 0.f;
            float c1 = (c + 1 <= r) ? acc1[mf][nf][1] : 0.f;
            float c2 = (c <= r + 8) ? acc1[mf][nf][2] : 0.f;
            float c3 = (c + 1 <= r + 8) ? acc1[mf][nf][3] : 0.f;
            uint32_t h, l;
            split2(c0, c1, h, l);
            *(uint32_t*)(sm + r * IMRB + c * 2)         = h;
            *(uint32_t*)(sm + 34816 + r * IMRB + c * 2) = l;
            split2(c2, c3, h, l);
            *(uint32_t*)(sm + (r + 8) * IMRB + c * 2)         = h;
            *(uint32_t*)(sm + 34816 + (r + 8) * IMRB + c * 2) = l;
        }
#pragma unroll
    for (int it = 0; it < 8; ++it) {
        int idx4 = it * 512 + tid, t = idx4 >> 5, c4 = (idx4 & 31) << 2;
        float4 b = *(const float4*)(vp + (size_t)t * 128 + c4);
        uint32_t h01, l01, h23, l23;
        split2(b.x, b.y, h01, l01); split2(b.z, b.w, h23, l23);
        *(uint2*)(sm + 139264 + t * IMRB + c4 * 2) = make_uint2(h01, h23);
        *(uint2*)(sm + 174080 + t * IMRB + c4 * 2) = make_uint2(l01, l23);
    }
    __syncthreads();

    // O2: acc2 += P @ V  (P natural in Q region; V natural -> trans B).
    gemm_tile<false, true>(sb + 0, sb + 34816, sb + 139264, sb + 174080, acc2, lane, m0, n0);

    float* op = out + (size_t)g * CE;
#pragma unroll
    for (int mf = 0; mf < 2; ++mf)
#pragma unroll
        for (int nf = 0; nf < 4; ++nf) {
            int r = m0 + mf * 16 + (lane >> 2), c = n0 + nf * 8 + (lane & 3) * 2;
            *(float2*)(op + (size_t)r * 128 + c)       = make_float2(acc2[mf][nf][0], acc2[mf][nf][1]);
            *(float2*)(op + (size_t)(r + 8) * 128 + c) = make_float2(acc2[mf][nf][2], acc2[mf][nf][3]);
        }
}

// ---------------------------------------------------------------------------

extern "C" void kernel_launch(void* const* d_in, const int* in_sizes, int n_in,
                              void* d_out, int out_size) {
    const float* q = (const float*)d_in[0];
    const float* k = (const float*)d_in[1];
    const float* v = (const float*)d_in[2];
    float* out = (float*)d_out;

    cudaFuncSetAttribute(kernA, cudaFuncAttributeMaxDynamicSharedMemorySize, A_SMEM);
    cudaFuncSetAttribute(kernC, cudaFuncAttributeMaxDynamicSharedMemorySize, C_SMEM);

    kernA<<<NCHUNK, 512, A_SMEM>>>(k, v);
    kernB<<<512, 256>>>();
    kernC<<<NCHUNK, 512, C_SMEM>>>(q, k, v, out);
}

// round 6
// speedup vs baseline: 1.8487x; 1.0515x over previous
#include <cuda_runtime.h>
#include <cuda_bf16.h>
#include <stdint.h>

// Linear causal attention, chunked states, bf16-split mma.sync.
//   O_c = Q_c @ S_c + (tril ⊙ Q_c K_c^T) @ V_c,  S_c = sum_{c'<c} K_{c'}^T V_{c'}
// fp32 GEMM = Ah*Bh + Ah*Bl + Al*Bh in bf16, fp32 accum. Operands natural [t][d];
// transposed fragments via ldmatrix.trans.

#define NCHUNK 1024
#define CE     16384
#define IMRB   272             // bytes per full image row (136 bf16)
#define IMU4   2176            // uint4 per 128-row full image
#define HPRB   144             // bytes per half image row (72 bf16)

__device__ float g_M[(size_t)NCHUNK * CE];        // K^T V per chunk, fp32
__device__ uint4 g_SH[(size_t)NCHUNK * IMU4];     // exclusive-prefix S, natural split images
__device__ uint4 g_SL[(size_t)NCHUNK * IMU4];

// ---------------- helpers ----------------
__device__ __forceinline__ uint32_t smem_u32(const void* p) {
    uint32_t a;
    asm("{ .reg .u64 t; cvta.to.shared.u64 t, %1; cvt.u32.u64 %0, t; }" : "=r"(a) : "l"(p));
    return a;
}
__device__ __forceinline__ void ldsm4(uint32_t a, uint32_t* r) {
    asm volatile("ldmatrix.sync.aligned.m8n8.x4.shared.b16 {%0,%1,%2,%3}, [%4];"
                 : "=r"(r[0]), "=r"(r[1]), "=r"(r[2]), "=r"(r[3]) : "r"(a));
}
__device__ __forceinline__ void ldsm4t(uint32_t a, uint32_t* r) {
    asm volatile("ldmatrix.sync.aligned.m8n8.x4.trans.shared.b16 {%0,%1,%2,%3}, [%4];"
                 : "=r"(r[0]), "=r"(r[1]), "=r"(r[2]), "=r"(r[3]) : "r"(a));
}
__device__ __forceinline__ void mma16816(float* c, const uint32_t* a, uint32_t b0, uint32_t b1) {
    asm volatile("mma.sync.aligned.m16n8k16.row.col.f32.bf16.bf16.f32 "
                 "{%0,%1,%2,%3}, {%4,%5,%6,%7}, {%8,%9}, {%0,%1,%2,%3};"
                 : "+f"(c[0]), "+f"(c[1]), "+f"(c[2]), "+f"(c[3])
                 : "r"(a[0]), "r"(a[1]), "r"(a[2]), "r"(a[3]), "r"(b0), "r"(b1));
}
__device__ __forceinline__ void split2(float x0, float x1, uint32_t& hi, uint32_t& lo) {
    __nv_bfloat16 h0 = __float2bfloat16_rn(x0), h1 = __float2bfloat16_rn(x1);
    __nv_bfloat16 l0 = __float2bfloat16_rn(x0 - __bfloat162float(h0));
    __nv_bfloat16 l1 = __float2bfloat16_rn(x1 - __bfloat162float(h1));
    hi = ((uint32_t)__bfloat16_as_ushort(h1) << 16) | (uint32_t)__bfloat16_as_ushort(h0);
    lo = ((uint32_t)__bfloat16_as_ushort(l1) << 16) | (uint32_t)__bfloat16_as_ushort(l0);
}

// C(32x32 warp tile) += [Ah|Ah|Al] x [Bh|Bl|Bh], K=128. TA/TB: operand image is
// natural [k][m] / [k][n] -> trans fragments. PA/PB: image row pitches (bytes).
template <bool TA, bool TB, int PA, int PB>
__device__ __forceinline__ void gemm_tile(uint32_t AH, uint32_t AL, uint32_t BH, uint32_t BL,
                                          float (&acc)[2][4][4], int lane, int m0, int n0) {
    const uint32_t a_lane = TA
        ? (uint32_t)(((lane & 7) + ((lane >> 4) << 3)) * PA + (((lane >> 3) & 1) << 4))
        : (uint32_t)((lane & 15) * PA + ((lane >> 4) << 4));
    const uint32_t b_lane = TB
        ? (uint32_t)(((lane & 7) + (((lane >> 3) & 1) << 3)) * PB + (((lane >> 4) & 1) << 4))
        : (uint32_t)(((lane & 7) + ((lane & 16) >> 1)) * PB + ((lane & 8) << 1));
    const uint32_t aH = AH + a_lane + (TA ? (uint32_t)m0 * 2 : (uint32_t)m0 * PA);
    const uint32_t aL = AL + a_lane + (TA ? (uint32_t)m0 * 2 : (uint32_t)m0 * PA);
    const uint32_t bH = BH + b_lane + (TB ? (uint32_t)n0 * 2 : (uint32_t)n0 * PB);
    const uint32_t bL = BL + b_lane + (TB ? (uint32_t)n0 * 2 : (uint32_t)n0 * PB);
    const uint32_t a_kb = TA ? 16 * PA : 32;
    const uint32_t a_mf = TA ? 32 : 16 * PA;
    const uint32_t b_kb = TB ? 16 * PB : 32;
    const uint32_t b_nh = TB ? 32 : 16 * PB;
#pragma unroll
    for (int kb = 0; kb < 8; ++kb) {
        uint32_t ah[2][4], al[2][4], bh[2][4], bl[2][4];
#pragma unroll
        for (int mf = 0; mf < 2; ++mf) {
            if (TA) { ldsm4t(aH + kb * a_kb + mf * a_mf, ah[mf]); ldsm4t(aL + kb * a_kb + mf * a_mf, al[mf]); }
            else    { ldsm4 (aH + kb * a_kb + mf * a_mf, ah[mf]); ldsm4 (aL + kb * a_kb + mf * a_mf, al[mf]); }
        }
#pragma unroll
        for (int nh = 0; nh < 2; ++nh) {
            if (TB) { ldsm4t(bH + kb * b_kb + nh * b_nh, bh[nh]); ldsm4t(bL + kb * b_kb + nh * b_nh, bl[nh]); }
            else    { ldsm4 (bH + kb * b_kb + nh * b_nh, bh[nh]); ldsm4 (bL + kb * b_kb + nh * b_nh, bl[nh]); }
        }
        // Term-outer: consecutive mmas never share an accumulator.
#pragma unroll
        for (int mf = 0; mf < 2; ++mf)
#pragma unroll
            for (int nf = 0; nf < 4; ++nf)
                mma16816(acc[mf][nf], ah[mf], bh[nf >> 1][(nf & 1) * 2], bh[nf >> 1][(nf & 1) * 2 + 1]);
#pragma unroll
        for (int mf = 0; mf < 2; ++mf)
#pragma unroll
            for (int nf = 0; nf < 4; ++nf)
                mma16816(acc[mf][nf], ah[mf], bl[nf >> 1][(nf & 1) * 2], bl[nf >> 1][(nf & 1) * 2 + 1]);
#pragma unroll
        for (int mf = 0; mf < 2; ++mf)
#pragma unroll
            for (int nf = 0; nf < 4; ++nf)
                mma16816(acc[mf][nf], al[mf], bh[nf >> 1][(nf & 1) * 2], bh[nf >> 1][(nf & 1) * 2 + 1]);
    }
}

// ---------------------------------------------------------------------------
// kernA: M_g = K_g^T V_g, in two 64-col halves of V/M so smem = 104 KB and
// 2 CTAs/SM overlap phases. 256 threads, 8 warps.
// smem: KH 0, KL 34816, VhH 69632 (18432), VhL 88064. Total 106496.
// ---------------------------------------------------------------------------
#define A_SMEM 106496
__global__ void __launch_bounds__(256, 2) kernA(const float* __restrict__ k,
                                                const float* __restrict__ v) {
    extern __shared__ char sm[];
    const uint32_t sb = smem_u32(sm);
    const int tid = threadIdx.x, lane = tid & 31, wid = tid >> 5;
    const int g = blockIdx.x;
    const float* kp = k + (size_t)g * CE;
    const float* vp = v + (size_t)g * CE;

    // Convert K full (natural): 4096 float4.
#pragma unroll
    for (int it = 0; it < 16; ++it) {
        int idx4 = it * 256 + tid, t = idx4 >> 5, c4 = (idx4 & 31) << 2;
        float4 a = *(const float4*)(kp + (size_t)t * 128 + c4);
        uint32_t h01, l01, h23, l23;
        split2(a.x, a.y, h01, l01); split2(a.z, a.w, h23, l23);
        *(uint2*)(sm + t * IMRB + c4 * 2)         = make_uint2(h01, h23);
        *(uint2*)(sm + 34816 + t * IMRB + c4 * 2) = make_uint2(l01, l23);
    }

    const int m0 = (wid & 3) * 32, n0 = (wid >> 2) * 32;
    float* mp = g_M + (size_t)g * CE;

#pragma unroll 1
    for (int h = 0; h < 2; ++h) {
        // Convert V half (cols h*64..h*64+63): 2048 float4.
#pragma unroll
        for (int it = 0; it < 8; ++it) {
            int idx4 = it * 256 + tid, t = idx4 >> 4, c4 = (idx4 & 15) << 2;
            float4 b = *(const float4*)(vp + (size_t)t * 128 + h * 64 + c4);
            uint32_t h01, l01, h23, l23;
            split2(b.x, b.y, h01, l01); split2(b.z, b.w, h23, l23);
            *(uint2*)(sm + 69632 + t * HPRB + c4 * 2) = make_uint2(h01, h23);
            *(uint2*)(sm + 88064 + t * HPRB + c4 * 2) = make_uint2(l01, l23);
        }
        __syncthreads();

        // M[:, h*64..] = K^T V_h : A trans (K natural), B trans (V natural).
        float acc[2][4][4] = {};
        gemm_tile<true, true, IMRB, HPRB>(sb + 0, sb + 34816, sb + 69632, sb + 88064,
                                          acc, lane, m0, n0);
#pragma unroll
        for (int mf = 0; mf < 2; ++mf)
#pragma unroll
            for (int nf = 0; nf < 4; ++nf) {
                int r = m0 + mf * 16 + (lane >> 2), c = h * 64 + n0 + nf * 8 + (lane & 3) * 2;
                *(float2*)(mp + (size_t)r * 128 + c)       = make_float2(acc[mf][nf][0], acc[mf][nf][1]);
                *(float2*)(mp + (size_t)(r + 8) * 128 + c) = make_float2(acc[mf][nf][2], acc[mf][nf][3]);
            }
        __syncthreads();   // guard V-half overwrite next iter
    }
}

// ---------------------------------------------------------------------------
// kernB: exclusive prefix over 16 chunk states per (b,h); natural split images.
// Grid 512 = 64 bh x 8 row-slices (16 d_k rows each).
// ---------------------------------------------------------------------------
__global__ void __launch_bounds__(256, 1) kernB() {
    __shared__ char sm[8704];                  // hi slice @0 (4352 B), lo @4352
    const int tid = threadIdx.x;
    const int bh = blockIdx.x >> 3, eb = blockIdx.x & 7;
    float run[8];
#pragma unroll
    for (int u = 0; u < 8; ++u) run[u] = 0.f;

    for (int c = 0; c < 16; ++c) {
        const float* Mc = g_M + ((size_t)bh * 16 + c) * CE;
        __syncthreads();
#pragma unroll
        for (int u = 0; u < 8; ++u) {
            int idx = u * 256 + tid;
            int dl = idx >> 7, e = idx & 127;
            float x = run[u];
            __nv_bfloat16 h = __float2bfloat16_rn(x);
            __nv_bfloat16 l = __float2bfloat16_rn(x - __bfloat162float(h));
            *(unsigned short*)(sm + dl * IMRB + e * 2)        = __bfloat16_as_ushort(h);
            *(unsigned short*)(sm + 4352 + dl * IMRB + e * 2) = __bfloat16_as_ushort(l);
            run[u] += Mc[(size_t)(eb * 16 + dl) * 128 + e];
        }
        __syncthreads();
        uint4* dh = g_SH + ((size_t)bh * 16 + c) * IMU4 + eb * 272;
        uint4* dl4 = g_SL + ((size_t)bh * 16 + c) * IMU4 + eb * 272;
        for (int i = tid; i < 272; i += 256) {
            dh[i]  = ((const uint4*)sm)[i];
            dl4[i] = ((const uint4*)(sm + 4352))[i];
        }
    }
}

// ---------------------------------------------------------------------------
// kernC: O = Q@S + (tril ⊙ QK^T)@V. 512 threads, 16 warps, 1 CTA/SM.
// smem: QH 0 (->P), QL 34816, KH 69632 (->V imgs), KL 104448,
//       SH 139264 (->V fp32 staging), SL 174080. Total 208896.
// ---------------------------------------------------------------------------
#define C_SMEM 208896
__global__ void __launch_bounds__(512, 1) kernC(const float* __restrict__ q,
                                                const float* __restrict__ k,
                                                const float* __restrict__ v,
                                                float* __restrict__ out) {
    extern __shared__ char sm[];
    const uint32_t sb = smem_u32(sm);
    const int tid = threadIdx.x, lane = tid & 31, wid = tid >> 5;
    const int g = blockIdx.x;
    const float* qp = q + (size_t)g * CE;
    const float* kp = k + (size_t)g * CE;
    const float* vp = v + (size_t)g * CE;

    // Async S images overlap the Q/K conversion.
    {
        const uint4* shh = g_SH + (size_t)g * IMU4;
        const uint4* sll = g_SL + (size_t)g * IMU4;
        for (int i = tid; i < IMU4; i += 512) {
            uint32_t d0 = sb + 139264 + i * 16, d1 = sb + 174080 + i * 16;
            asm volatile("cp.async.cg.shared.global [%0], [%1], 16;" :: "r"(d0), "l"(shh + i) : "memory");
            asm volatile("cp.async.cg.shared.global [%0], [%1], 16;" :: "r"(d1), "l"(sll + i) : "memory");
        }
        asm volatile("cp.async.commit_group;" ::: "memory");
    }
#pragma unroll
    for (int it = 0; it < 8; ++it) {
        int idx4 = it * 512 + tid, i = idx4 >> 5, c4 = (idx4 & 31) << 2;
        float4 a = *(const float4*)(qp + (size_t)i * 128 + c4);
        float4 b = *(const float4*)(kp + (size_t)i * 128 + c4);
        uint32_t h01, l01, h23, l23;
        split2(a.x, a.y, h01, l01); split2(a.z, a.w, h23, l23);
        *(uint2*)(sm + i * IMRB + c4 * 2)         = make_uint2(h01, h23);
        *(uint2*)(sm + 34816 + i * IMRB + c4 * 2) = make_uint2(l01, l23);
        split2(b.x, b.y, h01, l01); split2(b.z, b.w, h23, l23);
        *(uint2*)(sm + 69632 + i * IMRB + c4 * 2)  = make_uint2(h01, h23);
        *(uint2*)(sm + 104448 + i * IMRB + c4 * 2) = make_uint2(l01, l23);
    }
    asm volatile("cp.async.wait_group 0;" ::: "memory");
    __syncthreads();

    const int m0 = (wid & 3) * 32, n0 = (wid >> 2) * 32;

    // O1 = Q @ S (S natural -> trans B).
    float acc2[2][4][4] = {};
    gemm_tile<false, true, IMRB, IMRB>(sb + 0, sb + 34816, sb + 139264, sb + 174080,
                                       acc2, lane, m0, n0);
    __syncthreads();     // S region dead

    // Prefetch raw fp32 V (64 KB) into the S region; flies under the P GEMM.
    {
        const uint4* vp4 = (const uint4*)vp;
        for (int i = tid; i < 4096; i += 512) {
            uint32_t d0 = sb + 139264 + i * 16;
            asm volatile("cp.async.cg.shared.global [%0], [%1], 16;" :: "r"(d0), "l"(vp4 + i) : "memory");
        }
        asm volatile("cp.async.commit_group;" ::: "memory");
    }

    // P = Q K^T (both natural).
    float acc1[2][4][4] = {};
    gemm_tile<false, false, IMRB, IMRB>(sb + 0, sb + 34816, sb + 69632, sb + 104448,
                                        acc1, lane, m0, n0);
    asm volatile("cp.async.wait_group 0;" ::: "memory");
    __syncthreads();     // Q, K regions dead; V fp32 landed

    // Mask + split P into Q region; convert V (smem fp32) into K region images.
#pragma unroll
    for (int mf = 0; mf < 2; ++mf)
#pragma unroll
        for (int nf = 0; nf < 4; ++nf) {
            int r = m0 + mf * 16 + (lane >> 2), c = n0 + nf * 8 + (lane & 3) * 2;
            float c0 = (c <= r) ? acc1[mf][nf][0] : 0.f;
            float c1 = (c + 1 <= r) ? acc1[mf][nf][1] : 0.f;
            float c2 = (c <= r + 8) ? acc1[mf][nf][2] : 0.f;
            float c3 = (c + 1 <= r + 8) ? acc1[mf][nf][3] : 0.f;
            uint32_t h, l;
            split2(c0, c1, h, l);
            *(uint32_t*)(sm + r * IMRB + c * 2)         = h;
            *(uint32_t*)(sm + 34816 + r * IMRB + c * 2) = l;
            split2(c2, c3, h, l);
            *(uint32_t*)(sm + (r + 8) * IMRB + c * 2)         = h;
            *(uint32_t*)(sm + 34816 + (r + 8) * IMRB + c * 2) = l;
        }
    {
        const float* vf = (const float*)(sm + 139264);
#pragma unroll
        for (int it = 0; it < 8; ++it) {
            int idx4 = it * 512 + tid, t = idx4 >> 5, c4 = (idx4 & 31) << 2;
            float4 b = *(const float4*)(vf + idx4 * 4);
            uint32_t h01, l01, h23, l23;
            split2(b.x, b.y, h01, l01); split2(b.z, b.w, h23, l23);
            *(uint2*)(sm + 69632 + t * IMRB + c4 * 2)  = make_uint2(h01, h23);
            *(uint2*)(sm + 104448 + t * IMRB + c4 * 2) = make_uint2(l01, l23);
        }
    }
    __syncthreads();

    // O2: acc2 += P @ V (P natural in Q region; V images in K region, trans B).
    gemm_tile<false, true, IMRB, IMRB>(sb + 0, sb + 34816, sb + 69632, sb + 104448,
                                       acc2, lane, m0, n0);

    float* op = out + (size_t)g * CE;
#pragma unroll
    for (int mf = 0; mf < 2; ++mf)
#pragma unroll
        for (int nf = 0; nf < 4; ++nf) {
            int r = m0 + mf * 16 + (lane >> 2), c = n0 + nf * 8 + (lane & 3) * 2;
            *(float2*)(op + (size_t)r * 128 + c)       = make_float2(acc2[mf][nf][0], acc2[mf][nf][1]);
            *(float2*)(op + (size_t)(r + 8) * 128 + c) = make_float2(acc2[mf][nf][2], acc2[mf][nf][3]);
        }
}

// ---------------------------------------------------------------------------

extern "C" void kernel_launch(void* const* d_in, const int* in_sizes, int n_in,
                              void* d_out, int out_size) {
    const float* q = (const float*)d_in[0];
    const float* k = (const float*)d_in[1];
    const float* v = (const float*)d_in[2];
    float* out = (float*)d_out;

    cudaFuncSetAttribute(kernA, cudaFuncAttributeMaxDynamicSharedMemorySize, A_SMEM);
    cudaFuncSetAttribute(kernC, cudaFuncAttributeMaxDynamicSharedMemorySize, C_SMEM);

    kernA<<<NCHUNK, 256, A_SMEM>>>(k, v);
    kernB<<<512, 256>>>();
    kernC<<<NCHUNK, 512, C_SMEM>>>(q, k, v, out);
}

// round 7
// speedup vs baseline: 1.9718x; 1.0666x over previous
#include <cuda_runtime.h>
#include <cuda_bf16.h>
#include <stdint.h>

// Linear causal attention, chunked states, bf16-split mma.sync.
//   O_c = Q_c @ S_c + (tril ⊙ Q_c K_c^T) @ V_c,  S_c = sum_{c'<c} K_{c'}^T V_{c'}
// fp32 GEMM = Ah*Bh + Ah*Bl + Al*Bh in bf16, fp32 accum. Operands natural [t][d];
// transposed fragments via ldmatrix.trans. Causal structure: upper-triangle P
// tiles skipped, P@V k-loop truncated per row block.

#define NCHUNK 1024
#define CE     16384
#define IMRB   272             // bytes per full image row (136 bf16)
#define IMU4   2176            // uint4 per 128-row full image
#define HPRB   144             // bytes per half image row (72 bf16)

__device__ float g_M[(size_t)NCHUNK * CE];        // K^T V per chunk, fp32
__device__ uint4 g_SH[(size_t)NCHUNK * IMU4];     // exclusive-prefix S, natural split images
__device__ uint4 g_SL[(size_t)NCHUNK * IMU4];

// ---------------- helpers ----------------
__device__ __forceinline__ uint32_t smem_u32(const void* p) {
    uint32_t a;
    asm("{ .reg .u64 t; cvta.to.shared.u64 t, %1; cvt.u32.u64 %0, t; }" : "=r"(a) : "l"(p));
    return a;
}
__device__ __forceinline__ void ldsm4(uint32_t a, uint32_t* r) {
    asm volatile("ldmatrix.sync.aligned.m8n8.x4.shared.b16 {%0,%1,%2,%3}, [%4];"
                 : "=r"(r[0]), "=r"(r[1]), "=r"(r[2]), "=r"(r[3]) : "r"(a));
}
__device__ __forceinline__ void ldsm4t(uint32_t a, uint32_t* r) {
    asm volatile("ldmatrix.sync.aligned.m8n8.x4.trans.shared.b16 {%0,%1,%2,%3}, [%4];"
                 : "=r"(r[0]), "=r"(r[1]), "=r"(r[2]), "=r"(r[3]) : "r"(a));
}
__device__ __forceinline__ void mma16816(float* c, const uint32_t* a, uint32_t b0, uint32_t b1) {
    asm volatile("mma.sync.aligned.m16n8k16.row.col.f32.bf16.bf16.f32 "
                 "{%0,%1,%2,%3}, {%4,%5,%6,%7}, {%8,%9}, {%0,%1,%2,%3};"
                 : "+f"(c[0]), "+f"(c[1]), "+f"(c[2]), "+f"(c[3])
                 : "r"(a[0]), "r"(a[1]), "r"(a[2]), "r"(a[3]), "r"(b0), "r"(b1));
}
__device__ __forceinline__ void split2(float x0, float x1, uint32_t& hi, uint32_t& lo) {
    __nv_bfloat16 h0 = __float2bfloat16_rn(x0), h1 = __float2bfloat16_rn(x1);
    __nv_bfloat16 l0 = __float2bfloat16_rn(x0 - __bfloat162float(h0));
    __nv_bfloat16 l1 = __float2bfloat16_rn(x1 - __bfloat162float(h1));
    hi = ((uint32_t)__bfloat16_as_ushort(h1) << 16) | (uint32_t)__bfloat16_as_ushort(h0);
    lo = ((uint32_t)__bfloat16_as_ushort(l1) << 16) | (uint32_t)__bfloat16_as_ushort(l0);
}

// C(32x32 warp tile) += [Ah|Ah|Al] x [Bh|Bl|Bh] over kb_end 16-wide k-blocks.
// TA/TB: operand image natural [k][m]/[k][n] -> trans fragments. PA/PB pitches.
template <bool TA, bool TB, int PA, int PB, bool FULLK>
__device__ __forceinline__ void gemm_tile(uint32_t AH, uint32_t AL, uint32_t BH, uint32_t BL,
                                          float (&acc)[2][4][4], int lane, int m0, int n0,
                                          int kb_end) {
    const uint32_t a_lane = TA
        ? (uint32_t)(((lane & 7) + ((lane >> 4) << 3)) * PA + (((lane >> 3) & 1) << 4))
        : (uint32_t)((lane & 15) * PA + ((lane >> 4) << 4));
    const uint32_t b_lane = TB
        ? (uint32_t)(((lane & 7) + (((lane >> 3) & 1) << 3)) * PB + (((lane >> 4) & 1) << 4))
        : (uint32_t)(((lane & 7) + ((lane & 16) >> 1)) * PB + ((lane & 8) << 1));
    const uint32_t aH = AH + a_lane + (TA ? (uint32_t)m0 * 2 : (uint32_t)m0 * PA);
    const uint32_t aL = AL + a_lane + (TA ? (uint32_t)m0 * 2 : (uint32_t)m0 * PA);
    const uint32_t bH = BH + b_lane + (TB ? (uint32_t)n0 * 2 : (uint32_t)n0 * PB);
    const uint32_t bL = BL + b_lane + (TB ? (uint32_t)n0 * 2 : (uint32_t)n0 * PB);
    const uint32_t a_kb = TA ? 16 * PA : 32;
    const uint32_t a_mf = TA ? 32 : 16 * PA;
    const uint32_t b_kb = TB ? 16 * PB : 32;
    const uint32_t b_nh = TB ? 32 : 16 * PB;
#pragma unroll
    for (int kb = 0; kb < (FULLK ? 8 : 8); ++kb) {
        if (!FULLK && kb >= kb_end) break;
        uint32_t ah[2][4], al[2][4], bh[2][4], bl[2][4];
#pragma unroll
        for (int mf = 0; mf < 2; ++mf) {
            if (TA) { ldsm4t(aH + kb * a_kb + mf * a_mf, ah[mf]); ldsm4t(aL + kb * a_kb + mf * a_mf, al[mf]); }
            else    { ldsm4 (aH + kb * a_kb + mf * a_mf, ah[mf]); ldsm4 (aL + kb * a_kb + mf * a_mf, al[mf]); }
        }
#pragma unroll
        for (int nh = 0; nh < 2; ++nh) {
            if (TB) { ldsm4t(bH + kb * b_kb + nh * b_nh, bh[nh]); ldsm4t(bL + kb * b_kb + nh * b_nh, bl[nh]); }
            else    { ldsm4 (bH + kb * b_kb + nh * b_nh, bh[nh]); ldsm4 (bL + kb * b_kb + nh * b_nh, bl[nh]); }
        }
        // Term-outer: consecutive mmas never share an accumulator.
#pragma unroll
        for (int mf = 0; mf < 2; ++mf)
#pragma unroll
            for (int nf = 0; nf < 4; ++nf)
                mma16816(acc[mf][nf], ah[mf], bh[nf >> 1][(nf & 1) * 2], bh[nf >> 1][(nf & 1) * 2 + 1]);
#pragma unroll
        for (int mf = 0; mf < 2; ++mf)
#pragma unroll
            for (int nf = 0; nf < 4; ++nf)
                mma16816(acc[mf][nf], ah[mf], bl[nf >> 1][(nf & 1) * 2], bl[nf >> 1][(nf & 1) * 2 + 1]);
#pragma unroll
        for (int mf = 0; mf < 2; ++mf)
#pragma unroll
            for (int nf = 0; nf < 4; ++nf)
                mma16816(acc[mf][nf], al[mf], bh[nf >> 1][(nf & 1) * 2], bh[nf >> 1][(nf & 1) * 2 + 1]);
    }
}

// ---------------------------------------------------------------------------
// kernA: M_g = K_g^T V_g, two 64-col halves of V/M; 2 CTAs/SM, 256 threads.
// smem: KH 0, KL 34816, VhH 69632 (18432), VhL 88064. Total 106496.
// ---------------------------------------------------------------------------
#define A_SMEM 106496
__global__ void __launch_bounds__(256, 2) kernA(const float* __restrict__ k,
                                                const float* __restrict__ v) {
    extern __shared__ char sm[];
    const uint32_t sb = smem_u32(sm);
    const int tid = threadIdx.x, lane = tid & 31, wid = tid >> 5;
    const int g = blockIdx.x;
    const float* kp = k + (size_t)g * CE;
    const float* vp = v + (size_t)g * CE;

#pragma unroll
    for (int it = 0; it < 16; ++it) {
        int idx4 = it * 256 + tid, t = idx4 >> 5, c4 = (idx4 & 31) << 2;
        float4 a = *(const float4*)(kp + (size_t)t * 128 + c4);
        uint32_t h01, l01, h23, l23;
        split2(a.x, a.y, h01, l01); split2(a.z, a.w, h23, l23);
        *(uint2*)(sm + t * IMRB + c4 * 2)         = make_uint2(h01, h23);
        *(uint2*)(sm + 34816 + t * IMRB + c4 * 2) = make_uint2(l01, l23);
    }

    const int m0 = (wid & 3) * 32, n0 = (wid >> 2) * 32;
    float* mp = g_M + (size_t)g * CE;

#pragma unroll 1
    for (int h = 0; h < 2; ++h) {
#pragma unroll
        for (int it = 0; it < 8; ++it) {
            int idx4 = it * 256 + tid, t = idx4 >> 4, c4 = (idx4 & 15) << 2;
            float4 b = *(const float4*)(vp + (size_t)t * 128 + h * 64 + c4);
            uint32_t h01, l01, h23, l23;
            split2(b.x, b.y, h01, l01); split2(b.z, b.w, h23, l23);
            *(uint2*)(sm + 69632 + t * HPRB + c4 * 2) = make_uint2(h01, h23);
            *(uint2*)(sm + 88064 + t * HPRB + c4 * 2) = make_uint2(l01, l23);
        }
        __syncthreads();

        float acc[2][4][4] = {};
        gemm_tile<true, true, IMRB, HPRB, true>(sb + 0, sb + 34816, sb + 69632, sb + 88064,
                                                acc, lane, m0, n0, 8);
#pragma unroll
        for (int mf = 0; mf < 2; ++mf)
#pragma unroll
            for (int nf = 0; nf < 4; ++nf) {
                int r = m0 + mf * 16 + (lane >> 2), c = h * 64 + n0 + nf * 8 + (lane & 3) * 2;
                *(float2*)(mp + (size_t)r * 128 + c)       = make_float2(acc[mf][nf][0], acc[mf][nf][1]);
                *(float2*)(mp + (size_t)(r + 8) * 128 + c) = make_float2(acc[mf][nf][2], acc[mf][nf][3]);
            }
        __syncthreads();
    }
}

// ---------------------------------------------------------------------------
// kernB: exclusive prefix over 16 chunk states per (b,h); natural split images.
// Register double-buffer hides the per-chunk DRAM latency.
// Grid 512 = 64 bh x 8 row-slices (16 d_k rows each).
// ---------------------------------------------------------------------------
__global__ void __launch_bounds__(256, 1) kernB() {
    __shared__ char sm[8704];                  // hi slice @0 (4352 B), lo @4352
    const int tid = threadIdx.x;
    const int bh = blockIdx.x >> 3, eb = blockIdx.x & 7;
    float run[8], cur[8], nxt[8];
#pragma unroll
    for (int u = 0; u < 8; ++u) run[u] = 0.f;

    const size_t base = (size_t)bh * 16;
    // Preload chunk 0.
    {
        const float* M0 = g_M + base * CE;
#pragma unroll
        for (int u = 0; u < 8; ++u) {
            int idx = u * 256 + tid, dl = idx >> 7, e = idx & 127;
            cur[u] = M0[(size_t)(eb * 16 + dl) * 128 + e];
        }
    }
    for (int c = 0; c < 16; ++c) {
        // Issue next chunk's loads first (latency hidden behind convert+copy).
        const float* Mn = g_M + (base + (c < 15 ? c + 1 : c)) * CE;
#pragma unroll
        for (int u = 0; u < 8; ++u) {
            int idx = u * 256 + tid, dl = idx >> 7, e = idx & 127;
            nxt[u] = Mn[(size_t)(eb * 16 + dl) * 128 + e];
        }
        // Write exclusive-prefix images from run.
#pragma unroll
        for (int u = 0; u < 8; ++u) {
            int idx = u * 256 + tid, dl = idx >> 7, e = idx & 127;
            float x = run[u];
            __nv_bfloat16 h = __float2bfloat16_rn(x);
            __nv_bfloat16 l = __float2bfloat16_rn(x - __bfloat162float(h));
            *(unsigned short*)(sm + dl * IMRB + e * 2)        = __bfloat16_as_ushort(h);
            *(unsigned short*)(sm + 4352 + dl * IMRB + e * 2) = __bfloat16_as_ushort(l);
        }
        __syncthreads();
        uint4* dh = g_SH + (base + c) * IMU4 + eb * 272;
        uint4* dl4 = g_SL + (base + c) * IMU4 + eb * 272;
        for (int i = tid; i < 272; i += 256) {
            dh[i]  = ((const uint4*)sm)[i];
            dl4[i] = ((const uint4*)(sm + 4352))[i];
        }
#pragma unroll
        for (int u = 0; u < 8; ++u) { run[u] += cur[u]; cur[u] = nxt[u]; }
        __syncthreads();
    }
}

// ---------------------------------------------------------------------------
// kernC: O = Q@S + (tril ⊙ QK^T)@V. 512 threads, 16 warps, 1 CTA/SM.
// Warp tile map: mi = wid>>2, ni = (wid - mi) & 3  (SMSP-balanced Latin square).
// P chain skipped for ni>mi; O2 k-loop truncated to kb < 2*mi+2.
// smem: QH 0 (->P), QL 34816, KH 69632 (->V imgs), KL 104448,
//       SH 139264 (->V fp32 staging), SL 174080. Total 208896.
// ---------------------------------------------------------------------------
#define C_SMEM 208896
__global__ void __launch_bounds__(512, 1) kernC(const float* __restrict__ q,
                                                const float* __restrict__ k,
                                                const float* __restrict__ v,
                                                float* __restrict__ out) {
    extern __shared__ char sm[];
    const uint32_t sb = smem_u32(sm);
    const int tid = threadIdx.x, lane = tid & 31, wid = tid >> 5;
    const int g = blockIdx.x;
    const float* qp = q + (size_t)g * CE;
    const float* kp = k + (size_t)g * CE;
    const float* vp = v + (size_t)g * CE;

    // Async S images overlap the Q/K conversion.
    {
        const uint4* shh = g_SH + (size_t)g * IMU4;
        const uint4* sll = g_SL + (size_t)g * IMU4;
        for (int i = tid; i < IMU4; i += 512) {
            uint32_t d0 = sb + 139264 + i * 16, d1 = sb + 174080 + i * 16;
            asm volatile("cp.async.cg.shared.global [%0], [%1], 16;" :: "r"(d0), "l"(shh + i) : "memory");
            asm volatile("cp.async.cg.shared.global [%0], [%1], 16;" :: "r"(d1), "l"(sll + i) : "memory");
        }
        asm volatile("cp.async.commit_group;" ::: "memory");
    }
#pragma unroll
    for (int it = 0; it < 8; ++it) {
        int idx4 = it * 512 + tid, i = idx4 >> 5, c4 = (idx4 & 31) << 2;
        float4 a = *(const float4*)(qp + (size_t)i * 128 + c4);
        float4 b = *(const float4*)(kp + (size_t)i * 128 + c4);
        uint32_t h01, l01, h23, l23;
        split2(a.x, a.y, h01, l01); split2(a.z, a.w, h23, l23);
        *(uint2*)(sm + i * IMRB + c4 * 2)         = make_uint2(h01, h23);
        *(uint2*)(sm + 34816 + i * IMRB + c4 * 2) = make_uint2(l01, l23);
        split2(b.x, b.y, h01, l01); split2(b.z, b.w, h23, l23);
        *(uint2*)(sm + 69632 + i * IMRB + c4 * 2)  = make_uint2(h01, h23);
        *(uint2*)(sm + 104448 + i * IMRB + c4 * 2) = make_uint2(l01, l23);
    }
    asm volatile("cp.async.wait_group 0;" ::: "memory");
    __syncthreads();

    const int mi = wid >> 2, ni = (wid - mi) & 3;
    const int m0 = mi * 32, n0 = ni * 32;

    // O1 = Q @ S (S natural -> trans B).
    float acc2[2][4][4] = {};
    gemm_tile<false, true, IMRB, IMRB, true>(sb + 0, sb + 34816, sb + 139264, sb + 174080,
                                             acc2, lane, m0, n0, 8);
    __syncthreads();     // S region dead

    // Prefetch raw fp32 V (64 KB) into the S region; flies under the P GEMM.
    {
        const uint4* vp4 = (const uint4*)vp;
        for (int i = tid; i < 4096; i += 512) {
            uint32_t d0 = sb + 139264 + i * 16;
            asm volatile("cp.async.cg.shared.global [%0], [%1], 16;" :: "r"(d0), "l"(vp4 + i) : "memory");
        }
        asm volatile("cp.async.commit_group;" ::: "memory");
    }

    // P = Q K^T (both natural). Tiles strictly above the diagonal are all-zero.
    float acc1[2][4][4] = {};
    if (ni <= mi)
        gemm_tile<false, false, IMRB, IMRB, true>(sb + 0, sb + 34816, sb + 69632, sb + 104448,
                                                  acc1, lane, m0, n0, 8);
    asm volatile("cp.async.wait_group 0;" ::: "memory");
    __syncthreads();     // Q, K regions dead; V fp32 landed

    // Mask + split P into Q region (only tiles that exist); convert V into K region.
    if (ni <= mi) {
#pragma unroll
        for (int mf = 0; mf < 2; ++mf)
#pragma unroll
            for (int nf = 0; nf < 4; ++nf) {
                int r = m0 + mf * 16 + (lane >> 2), c = n0 + nf * 8 + (lane & 3) * 2;
                float c0 = (c <= r) ? acc1[mf][nf][0] : 0.f;
                float c1 = (c + 1 <= r) ? acc1[mf][nf][1] : 0.f;
                float c2 = (c <= r + 8) ? acc1[mf][nf][2] : 0.f;
                float c3 = (c + 1 <= r + 8) ? acc1[mf][nf][3] : 0.f;
                uint32_t h, l;
                split2(c0, c1, h, l);
                *(uint32_t*)(sm + r * IMRB + c * 2)         = h;
                *(uint32_t*)(sm + 34816 + r * IMRB + c * 2) = l;
                split2(c2, c3, h, l);
                *(uint32_t*)(sm + (r + 8) * IMRB + c * 2)         = h;
                *(uint32_t*)(sm + 34816 + (r + 8) * IMRB + c * 2) = l;
            }
    }
    {
        const float* vf = (const float*)(sm + 139264);
#pragma unroll
        for (int it = 0; it < 8; ++it) {
            int idx4 = it * 512 + tid, t = idx4 >> 5, c4 = (idx4 & 31) << 2;
            float4 b = *(const float4*)(vf + idx4 * 4);
            uint32_t h01, l01, h23, l23;
            split2(b.x, b.y, h01, l01); split2(b.z, b.w, h23, l23);
            *(uint2*)(sm + 69632 + t * IMRB + c4 * 2)  = make_uint2(h01, h23);
            *(uint2*)(sm + 104448 + t * IMRB + c4 * 2) = make_uint2(l01, l23);
        }
    }
    __syncthreads();

    // O2: acc2 += P @ V, k truncated to the nonzero column range of this row block.
    gemm_tile<false, true, IMRB, IMRB, false>(sb + 0, sb + 34816, sb + 69632, sb + 104448,
                                              acc2, lane, m0, n0, 2 * mi + 2);

    float* op = out + (size_t)g * CE;
#pragma unroll
    for (int mf = 0; mf < 2; ++mf)
#pragma unroll
        for (int nf = 0; nf < 4; ++nf) {
            int r = m0 + mf * 16 + (lane >> 2), c = n0 + nf * 8 + (lane & 3) * 2;
            *(float2*)(op + (size_t)r * 128 + c)       = make_float2(acc2[mf][nf][0], acc2[mf][nf][1]);
            *(float2*)(op + (size_t)(r + 8) * 128 + c) = make_float2(acc2[mf][nf][2], acc2[mf][nf][3]);
        }
}

// ---------------------------------------------------------------------------

extern "C" void kernel_launch(void* const* d_in, const int* in_sizes, int n_in,
                              void* d_out, int out_size) {
    const float* q = (const float*)d_in[0];
    const float* k = (const float*)d_in[1];
    const float* v = (const float*)d_in[2];
    float* out = (float*)d_out;

    cudaFuncSetAttribute(kernA, cudaFuncAttributeMaxDynamicSharedMemorySize, A_SMEM);
    cudaFuncSetAttribute(kernC, cudaFuncAttributeMaxDynamicSharedMemorySize, C_SMEM);

    kernA<<<NCHUNK, 256, A_SMEM>>>(k, v);
    kernB<<<512, 256>>>();
    kernC<<<NCHUNK, 512, C_SMEM>>>(q, k, v, out);
}